// round 1
// baseline (speedup 1.0000x reference)
#include <cuda_runtime.h>

// ---------------- problem constants ----------------
#define B_    8
#define C_    1024       // INPUT_DIM
#define HW_   4096       // H*W
#define L_    4096       // sequence length = H*W
#define D_    1024       // DIM
#define N_    256        // N_SLOTS
#define MLP_  512        // MLP_DIM
#define TITER 6
#define EPS_  1e-5f
#define SCALE_ 0.03125f  // DIM^-0.5

// ---------------- scratch (device globals; no allocation allowed) ----------------
__device__ float g_mu[B_*L_];
__device__ float g_rstd[B_*L_];
__device__ float g_xn[(size_t)B_*L_*C_];     // 128 MB
__device__ float g_k [(size_t)B_*L_*D_];     // 128 MB
__device__ float g_v [(size_t)B_*L_*D_];     // 128 MB
__device__ float g_tmpl[B_*N_*D_];           // templates
__device__ float g_t2  [B_*N_*D_];           // LN(templates) scratch (tln / mln)
__device__ float g_q   [B_*N_*D_];
__device__ float g_attn[(size_t)B_*L_*N_];   // logits -> attn (32 MB)
__device__ float g_cspart[B_*16*N_];
__device__ float g_csinv[B_*N_];
__device__ float g_h[B_*N_*MLP_];

// ---------------- input LN stats: thread per (b,l), coalesced over l ----------------
__global__ void input_stats(const float* __restrict__ x) {
    int gid = blockIdx.x * blockDim.x + threadIdx.x;  // [0, B*L)
    int b = gid >> 12;
    int l = gid & (L_ - 1);
    const float* p = x + (size_t)b * C_ * HW_ + l;
    float s = 0.f, ss = 0.f;
    #pragma unroll 8
    for (int c = 0; c < C_; c++) {
        float v = p[(size_t)c * HW_];
        s += v; ss += v * v;
    }
    float mu = s * (1.f / C_);
    float var = ss * (1.f / C_) - mu * mu;
    g_mu[gid] = mu;
    g_rstd[gid] = rsqrtf(fmaxf(var, 0.f) + EPS_);
}

// ---------------- transpose + normalize: x[b,c,l] -> xn[b,l,c] ----------------
__global__ void transpose_norm(const float* __restrict__ x,
                               const float* __restrict__ gamma,
                               const float* __restrict__ beta) {
    __shared__ float tile[32][33];
    int b  = blockIdx.z;
    int l0 = blockIdx.x * 32;
    int c0 = blockIdx.y * 32;
    int tx = threadIdx.x, ty = threadIdx.y;
    const float* xb = x + (size_t)b * C_ * HW_;
    #pragma unroll
    for (int r = 0; r < 4; r++)
        tile[ty + 8*r][tx] = xb[(size_t)(c0 + ty + 8*r) * HW_ + l0 + tx];
    __syncthreads();
    #pragma unroll
    for (int r = 0; r < 4; r++) {
        int l = l0 + ty + 8*r;
        int c = c0 + tx;
        float mu = g_mu[b*L_ + l];
        float rs = g_rstd[b*L_ + l];
        g_xn[((size_t)(b*L_ + l)) * C_ + c] =
            (tile[tx][ty + 8*r] - mu) * rs * gamma[c] + beta[c];
    }
}

// ---------------- broadcast templates_init ----------------
__global__ void bcast_tmpl(const float* __restrict__ ti) {
    int i = blockIdx.x * 256 + threadIdx.x;  // B*N*D threads
    g_tmpl[i] = ti[i & (N_*D_ - 1)];
}

// ---------------- block reduction ----------------
__device__ __forceinline__ float block_sum(float v) {
    __shared__ float sh[8];
    __shared__ float tot;
    #pragma unroll
    for (int o = 16; o; o >>= 1) v += __shfl_xor_sync(0xffffffffu, v, o);
    if ((threadIdx.x & 31) == 0) sh[threadIdx.x >> 5] = v;
    __syncthreads();
    if (threadIdx.x == 0) {
        float s = 0.f;
        #pragma unroll
        for (int i = 0; i < 8; i++) s += sh[i];
        tot = s;
    }
    __syncthreads();
    return tot;
}

// ---------------- row LayerNorm over 1024 cols (256 threads, float4/thread) ----------------
__global__ void ln_rows(const float* __restrict__ in, float* __restrict__ out,
                        const float* __restrict__ gamma, const float* __restrict__ beta) {
    int row = blockIdx.x;
    int t = threadIdx.x;
    float4 v = ((const float4*)(in + (size_t)row * 1024))[t];
    float s = block_sum(v.x + v.y + v.z + v.w);
    float mu = s * (1.f / 1024.f);
    float dx = v.x - mu, dy = v.y - mu, dz = v.z - mu, dw = v.w - mu;
    float ss = block_sum(dx*dx + dy*dy + dz*dz + dw*dw);
    float rs = rsqrtf(ss * (1.f / 1024.f) + EPS_);
    float4 g4 = ((const float4*)gamma)[t];
    float4 b4 = ((const float4*)beta)[t];
    float4 o;
    o.x = dx * rs * g4.x + b4.x;
    o.y = dy * rs * g4.y + b4.y;
    o.z = dz * rs * g4.z + b4.z;
    o.w = dw * rs * g4.w + b4.w;
    ((float4*)(out + (size_t)row * 1024))[t] = o;
}

// ---------------- generic tiled SGEMM ----------------
// C[m,n] = epilogue( sum_k A(m,k) * B(k,n) )
// A(m,k) = TA ? A[(k)*lda + m] : A[(m)*lda + k]
// B(k,n) = TB ? B[(n)*ldb + k] : B[(k)*ldb + n]
// EPI: 0: C = alpha*acc
//      2: C = res[m,n] + rowscale[m]*acc
//      3: C = relu(acc + bias[n])
//      4: C = res[m,n] + acc + bias[n]
template<int TA, int TB, int EPI>
__global__ void gemm(const float* __restrict__ A, const float* __restrict__ Bm,
                     float* __restrict__ Cm, int M, int N, int K,
                     int lda, int ldb, int ldc,
                     long long sA, long long sB, long long sC,
                     const float* __restrict__ res,
                     const float* __restrict__ rowscale, long long sRow,
                     const float* __restrict__ bias, float alpha) {
    __shared__ float As[16][132];
    __shared__ float Bs[16][132];
    int bz = blockIdx.z;
    A  += (size_t)bz * sA;
    Bm += (size_t)bz * sB;
    Cm += (size_t)bz * sC;
    if (EPI == 2 || EPI == 4) res += (size_t)bz * sC;
    if (EPI == 2) rowscale += (size_t)bz * sRow;

    int m0 = blockIdx.y * 128;
    int n0 = blockIdx.x * 128;
    int t  = threadIdx.x;           // 256 threads
    int tx = t & 15, ty = t >> 4;   // 16x16 grid of 8x8 microtiles

    float acc[8][8];
    #pragma unroll
    for (int i = 0; i < 8; i++)
        #pragma unroll
        for (int j = 0; j < 8; j++) acc[i][j] = 0.f;

    for (int k0 = 0; k0 < K; k0 += 16) {
        #pragma unroll
        for (int f = 0; f < 2; f++) {
            int fi = t + f * 256;   // 512 float4 loads per tile
            // ---- A tile -> As[k][m] ----
            if (TA == 0) {
                int row = fi >> 2, kq = (fi & 3) * 4;
                float4 v = *(const float4*)&A[(size_t)(m0 + row) * lda + k0 + kq];
                As[kq + 0][row] = v.x; As[kq + 1][row] = v.y;
                As[kq + 2][row] = v.z; As[kq + 3][row] = v.w;
            } else {
                int k = fi >> 5, mq = (fi & 31) * 4;
                float4 v = *(const float4*)&A[(size_t)(k0 + k) * lda + m0 + mq];
                As[k][mq + 0] = v.x; As[k][mq + 1] = v.y;
                As[k][mq + 2] = v.z; As[k][mq + 3] = v.w;
            }
            // ---- B tile -> Bs[k][n] ----
            if (TB == 0) {
                int k = fi >> 5, nq = (fi & 31) * 4;
                float4 v = *(const float4*)&Bm[(size_t)(k0 + k) * ldb + n0 + nq];
                Bs[k][nq + 0] = v.x; Bs[k][nq + 1] = v.y;
                Bs[k][nq + 2] = v.z; Bs[k][nq + 3] = v.w;
            } else {
                int row = fi >> 2, kq = (fi & 3) * 4;
                float4 v = *(const float4*)&Bm[(size_t)(n0 + row) * ldb + k0 + kq];
                Bs[kq + 0][row] = v.x; Bs[kq + 1][row] = v.y;
                Bs[kq + 2][row] = v.z; Bs[kq + 3][row] = v.w;
            }
        }
        __syncthreads();
        #pragma unroll
        for (int k = 0; k < 16; k++) {
            float a[8], b[8];
            #pragma unroll
            for (int i = 0; i < 8; i++) a[i] = As[k][ty * 8 + i];
            #pragma unroll
            for (int j = 0; j < 8; j++) b[j] = Bs[k][tx * 8 + j];
            #pragma unroll
            for (int i = 0; i < 8; i++)
                #pragma unroll
                for (int j = 0; j < 8; j++) acc[i][j] += a[i] * b[j];
        }
        __syncthreads();
    }

    #pragma unroll
    for (int i = 0; i < 8; i++) {
        int m = m0 + ty * 8 + i;
        float rsc = (EPI == 2) ? rowscale[m] : 1.f;
        #pragma unroll
        for (int j = 0; j < 8; j++) {
            int n = n0 + tx * 8 + j;
            size_t idx = (size_t)m * ldc + n;
            float v = acc[i][j];
            if (EPI == 0)      Cm[idx] = v * alpha;
            else if (EPI == 2) Cm[idx] = res[idx] + rsc * v;
            else if (EPI == 3) Cm[idx] = fmaxf(v + bias[n], 0.f);
            else if (EPI == 4) Cm[idx] = res[idx] + v + bias[n];
        }
    }
}

// ---------------- softmax over N=256 (warp per row) + 1e-8 ----------------
__global__ void softmax_rows(float* __restrict__ p) {
    int warp = threadIdx.x >> 5, lane = threadIdx.x & 31;
    int row = blockIdx.x * 8 + warp;   // rows = B*L
    float* r = p + (size_t)row * 256;
    float4 a = ((float4*)r)[lane];
    float4 b = ((float4*)r)[32 + lane];
    float mx = fmaxf(fmaxf(fmaxf(a.x, a.y), fmaxf(a.z, a.w)),
                     fmaxf(fmaxf(b.x, b.y), fmaxf(b.z, b.w)));
    #pragma unroll
    for (int o = 16; o; o >>= 1) mx = fmaxf(mx, __shfl_xor_sync(0xffffffffu, mx, o));
    a.x = __expf(a.x - mx); a.y = __expf(a.y - mx);
    a.z = __expf(a.z - mx); a.w = __expf(a.w - mx);
    b.x = __expf(b.x - mx); b.y = __expf(b.y - mx);
    b.z = __expf(b.z - mx); b.w = __expf(b.w - mx);
    float s = a.x + a.y + a.z + a.w + b.x + b.y + b.z + b.w;
    #pragma unroll
    for (int o = 16; o; o >>= 1) s += __shfl_xor_sync(0xffffffffu, s, o);
    float inv = 1.f / s;
    a.x = a.x * inv + 1e-8f; a.y = a.y * inv + 1e-8f;
    a.z = a.z * inv + 1e-8f; a.w = a.w * inv + 1e-8f;
    b.x = b.x * inv + 1e-8f; b.y = b.y * inv + 1e-8f;
    b.z = b.z * inv + 1e-8f; b.w = b.w * inv + 1e-8f;
    ((float4*)r)[lane] = a;
    ((float4*)r)[32 + lane] = b;
}

// ---------------- column-sum over L (two stages) -> 1/colsum ----------------
__global__ void colsum_part() {
    int chunk = blockIdx.x, b = blockIdx.y, n = threadIdx.x;
    const float* p = g_attn + (size_t)b * L_ * N_ + (size_t)chunk * 256 * N_ + n;
    float s = 0.f;
    #pragma unroll 8
    for (int l = 0; l < 256; l++) s += p[(size_t)l * N_];
    g_cspart[(b * 16 + chunk) * N_ + n] = s;
}
__global__ void colsum_fin() {
    int b = blockIdx.x, n = threadIdx.x;
    float s = 0.f;
    #pragma unroll
    for (int i = 0; i < 16; i++) s += g_cspart[(b * 16 + i) * N_ + n];
    g_csinv[b * N_ + n] = 1.f / s;
}

// ---------------- output transposes ----------------
__global__ void out_templates_k(float* __restrict__ out) {
    __shared__ float tile[32][33];
    int b = blockIdx.z;
    int n0 = blockIdx.x * 32, d0 = blockIdx.y * 32;
    int tx = threadIdx.x, ty = threadIdx.y;
    const float* tp = g_tmpl + (size_t)b * N_ * D_;
    #pragma unroll
    for (int r = 0; r < 4; r++)
        tile[ty + 8*r][tx] = tp[(size_t)(n0 + ty + 8*r) * D_ + d0 + tx];
    __syncthreads();
    float* op = out + (size_t)b * D_ * N_;
    #pragma unroll
    for (int r = 0; r < 4; r++)
        op[(size_t)(d0 + ty + 8*r) * N_ + n0 + tx] = tile[tx][ty + 8*r];
}

__global__ void out_attn_k(float* __restrict__ out) {
    __shared__ float tile[32][33];
    int b = blockIdx.z;
    int l0 = blockIdx.x * 32, n0 = blockIdx.y * 32;
    int tx = threadIdx.x, ty = threadIdx.y;
    const float* ap = g_attn + (size_t)b * L_ * N_;
    #pragma unroll
    for (int r = 0; r < 4; r++)
        tile[ty + 8*r][tx] = ap[(size_t)(l0 + ty + 8*r) * N_ + n0 + tx];
    __syncthreads();
    float* op = out + (size_t)b * N_ * HW_;
    #pragma unroll
    for (int r = 0; r < 4; r++) {
        int n = n0 + ty + 8*r;
        op[(size_t)n * HW_ + l0 + tx] = tile[tx][ty + 8*r] * g_csinv[b * N_ + n];
    }
}

// ---------------- launch ----------------
extern "C" void kernel_launch(void* const* d_in, const int* in_sizes, int n_in,
                              void* d_out, int out_size) {
    const float* x      = (const float*)d_in[0];
    const float* ti     = (const float*)d_in[1];
    const float* Wq     = (const float*)d_in[2];
    const float* Wk     = (const float*)d_in[3];
    const float* Wv     = (const float*)d_in[4];
    const float* lin_g  = (const float*)d_in[5];
    const float* lin_b  = (const float*)d_in[6];
    const float* lt_g   = (const float*)d_in[7];
    const float* lt_b   = (const float*)d_in[8];
    const float* lm_g   = (const float*)d_in[9];
    const float* lm_b   = (const float*)d_in[10];
    const float* W1     = (const float*)d_in[11];
    const float* b1     = (const float*)d_in[12];
    const float* W2     = (const float*)d_in[13];
    const float* b2     = (const float*)d_in[14];
    float* out_t = (float*)d_out;                          // [B, D, N]
    float* out_a = (float*)d_out + (size_t)B_ * D_ * N_;   // [B, N, H, W]

    float *p_xn, *p_k, *p_v, *p_tmpl, *p_t2, *p_q, *p_attn, *p_csinv, *p_h;
    cudaGetSymbolAddress((void**)&p_xn, g_xn);
    cudaGetSymbolAddress((void**)&p_k, g_k);
    cudaGetSymbolAddress((void**)&p_v, g_v);
    cudaGetSymbolAddress((void**)&p_tmpl, g_tmpl);
    cudaGetSymbolAddress((void**)&p_t2, g_t2);
    cudaGetSymbolAddress((void**)&p_q, g_q);
    cudaGetSymbolAddress((void**)&p_attn, g_attn);
    cudaGetSymbolAddress((void**)&p_csinv, g_csinv);
    cudaGetSymbolAddress((void**)&p_h, g_h);

    dim3 tb32(32, 8);

    // input LN + transpose
    input_stats<<<(B_ * L_) / 256, 256>>>(x);
    transpose_norm<<<dim3(HW_ / 32, C_ / 32, B_), tb32>>>(x, lin_g, lin_b);

    // k, v projections: [32768,1024] x [1024,1024]
    gemm<0,0,0><<<dim3(1024/128, 32768/128, 1), 256>>>(
        p_xn, Wk, p_k, 32768, 1024, 1024, 1024, 1024, 1024,
        0, 0, 0, nullptr, nullptr, 0, nullptr, 1.f);
    gemm<0,0,0><<<dim3(1024/128, 32768/128, 1), 256>>>(
        p_xn, Wv, p_v, 32768, 1024, 1024, 1024, 1024, 1024,
        0, 0, 0, nullptr, nullptr, 0, nullptr, 1.f);

    bcast_tmpl<<<(B_ * N_ * D_) / 256, 256>>>(ti);

    for (int it = 0; it < TITER; it++) {
        // t = LN(templates); q = t @ Wq * scale
        ln_rows<<<B_ * N_, 256>>>(p_tmpl, p_t2, lt_g, lt_b);
        gemm<0,0,0><<<dim3(1024/128, 2048/128, 1), 256>>>(
            p_t2, Wq, p_q, 2048, 1024, 1024, 1024, 1024, 1024,
            0, 0, 0, nullptr, nullptr, 0, nullptr, SCALE_);

        // logits[b] = k[b] @ q[b]^T : [4096,1024] x [1024,256]
        gemm<0,1,0><<<dim3(256/128, 4096/128, B_), 256>>>(
            p_k, p_q, p_attn, 4096, 256, 1024, 1024, 1024, 256,
            (long long)L_ * D_, (long long)N_ * D_, (long long)L_ * N_,
            nullptr, nullptr, 0, nullptr, 1.f);

        softmax_rows<<<(B_ * L_) / 8, 256>>>(p_attn);
        colsum_part<<<dim3(16, B_), 256>>>();
        colsum_fin<<<B_, 256>>>();

        // templates += rowscale[n] * (attn^T @ v) : [256,4096]^T x [4096,1024]
        gemm<1,0,2><<<dim3(1024/128, 256/128, B_), 256>>>(
            p_attn, p_v, p_tmpl, 256, 1024, 4096, 256, 1024, 1024,
            (long long)L_ * N_, (long long)L_ * D_, (long long)N_ * D_,
            p_tmpl, p_csinv, N_, nullptr, 1.f);

        // MLP: m = LN(templates); templates += relu(m@W1+b1)@W2 + b2
        ln_rows<<<B_ * N_, 256>>>(p_tmpl, p_t2, lm_g, lm_b);
        gemm<0,0,3><<<dim3(512/128, 2048/128, 1), 256>>>(
            p_t2, W1, p_h, 2048, 512, 1024, 1024, 512, 512,
            0, 0, 0, nullptr, nullptr, 0, b1, 1.f);
        gemm<0,0,4><<<dim3(1024/128, 2048/128, 1), 256>>>(
            p_h, W2, p_tmpl, 2048, 1024, 512, 512, 1024, 1024,
            0, 0, 0, p_tmpl, nullptr, 0, b2, 1.f);
    }

    out_templates_k<<<dim3(N_ / 32, D_ / 32, B_), tb32>>>(out_t);
    out_attn_k<<<dim3(L_ / 32, N_ / 32, B_), tb32>>>(out_a);
}

// round 3
// speedup vs baseline: 3.4049x; 3.4049x over previous
#include <cuda_runtime.h>
#include <cstdint>

// ---------------- problem constants ----------------
#define B_    8
#define C_    1024       // INPUT_DIM
#define HW_   4096       // H*W
#define L_    4096       // sequence length = H*W
#define D_    1024       // DIM
#define N_    256        // N_SLOTS
#define MLP_  512        // MLP_DIM
#define TITER 6
#define EPS_  1e-5f
#define SCALE_ 0.03125f  // DIM^-0.5

// ---------------- scratch (device globals; no allocation allowed) ----------------
__device__ float g_mu[B_*L_];
__device__ float g_rstd[B_*L_];
__device__ float g_xn[(size_t)B_*L_*C_];
__device__ float g_k [(size_t)B_*L_*D_];
__device__ float g_v [(size_t)B_*L_*D_];
__device__ float g_vT[(size_t)B_*D_*L_];
__device__ float g_tmpl[B_*N_*D_];
__device__ float g_t2  [B_*N_*D_];
__device__ float g_q   [B_*N_*D_];
__device__ float g_attn [(size_t)B_*L_*N_];
__device__ float g_attnT[(size_t)B_*N_*L_];
__device__ float g_csinv[B_*N_];
__device__ float g_h[B_*N_*MLP_];
__device__ float g_WqT[D_*D_];
__device__ float g_WkT[D_*C_];
__device__ float g_WvT[D_*C_];
__device__ float g_W1T[MLP_*D_];
__device__ float g_W2T[D_*MLP_];

// ---------------- helpers ----------------
__device__ __forceinline__ float tf32r(float x) {
    float y;
    asm("cvt.rna.tf32.f32 %0, %1;" : "=f"(y) : "f"(x));
    return y;
}
__device__ __forceinline__ uint32_t smem_u32(const void* p) {
    uint32_t a;
    asm("{ .reg .u64 t; cvta.to.shared.u64 t, %1; cvt.u32.u64 %0, t; }" : "=r"(a) : "l"(p));
    return a;
}
__device__ __forceinline__ void cp16(uint32_t s, const float* g) {
    asm volatile("cp.async.cg.shared.global [%0], [%1], 16;\n" :: "r"(s), "l"(g));
}
#define CP_COMMIT() asm volatile("cp.async.commit_group;\n" ::: "memory")
#define CP_WAIT(N)  asm volatile("cp.async.wait_group %0;\n" :: "n"(N) : "memory")

// ================= tensor-core GEMM (mma.sync tf32) =================
// C[M,N] = epi( A[M,K] @ B[N,K]^T ); A,B K-major fp32 already tf32-rounded.
// CTA tile 128x128, KC=32, double-buffered cp.async.
// Warps: 4(M) x 2(N); warp tile 32x64; mma m16n8k8.
// EPI: 0: alpha*acc   2: res + rowscale[m]*acc   3: relu(acc+bias)   4: res+acc+bias
#define KC_ 32
#define ASTRIDE 36                 // padded floats per row (conflict-free frags)
#define STAGEF (128 * ASTRIDE)     // 4608 floats per operand stage

template<int EPI, int RND>
__global__ void __launch_bounds__(256, 2)
tgemm(const float* __restrict__ A, const float* __restrict__ Bm,
      float* __restrict__ Cm, int K, int ldc,
      long long sA, long long sB, long long sC,
      const float* __restrict__ res, const float* __restrict__ rowscale,
      long long sRow, const float* __restrict__ bias, float alpha) {
    extern __shared__ float sm[];
    const uint32_t asu = smem_u32(sm);

    const int tid  = threadIdx.x;
    const int wid  = tid >> 5;
    const int lane = tid & 31;
    const int wm = (wid >> 1) * 32;   // warp row offset in tile
    const int wn = (wid & 1) * 64;    // warp col offset in tile

    const int bz = blockIdx.z;
    A  += (size_t)bz * sA;
    Bm += (size_t)bz * sB;
    Cm += (size_t)bz * sC;
    if (EPI == 2 || EPI == 4) res += (size_t)bz * sC;
    if (EPI == 2) rowscale += (size_t)bz * sRow;

    const int m0 = blockIdx.y * 128;
    const int n0 = blockIdx.x * 128;
    const float* gA = A + (size_t)m0 * K;
    const float* gB = Bm + (size_t)n0 * K;

    float acc[2][8][4];
    #pragma unroll
    for (int i = 0; i < 2; i++)
        #pragma unroll
        for (int j = 0; j < 8; j++)
            #pragma unroll
            for (int r = 0; r < 4; r++) acc[i][j][r] = 0.f;

    auto load_chunk = [&](int c) {
        int buf = c & 1;
        uint32_t as = asu + (uint32_t)(buf * STAGEF) * 4u;
        uint32_t bs = asu + (uint32_t)(2 * STAGEF + buf * STAGEF) * 4u;
        const float* ga = gA + c * KC_;
        const float* gb = gB + c * KC_;
        #pragma unroll
        for (int i = 0; i < 4; i++) {
            int e = tid + i * 256;
            int row = e >> 3;
            int q = (e & 7) * 4;
            uint32_t so = (uint32_t)(row * ASTRIDE + q) * 4u;
            cp16(as + so, ga + (size_t)row * K + q);
            cp16(bs + so, gb + (size_t)row * K + q);
        }
        CP_COMMIT();
    };

    const int NC = K / KC_;
    load_chunk(0);

    for (int c = 0; c < NC; c++) {
        if (c + 1 < NC) { load_chunk(c + 1); CP_WAIT(1); }
        else            { CP_WAIT(0); }
        __syncthreads();

        int buf = c & 1;
        const float* ap = sm + buf * STAGEF + (wm + (lane >> 2)) * ASTRIDE + (lane & 3);
        const float* bp = sm + 2 * STAGEF + buf * STAGEF + (wn + (lane >> 2)) * ASTRIDE + (lane & 3);

        #pragma unroll
        for (int ks = 0; ks < 4; ks++) {
            const int k0 = ks * 8;
            uint32_t a[2][4], b[8][2];
            #pragma unroll
            for (int mf = 0; mf < 2; mf++) {
                a[mf][0] = __float_as_uint(ap[(mf * 16 + 0) * ASTRIDE + k0]);
                a[mf][1] = __float_as_uint(ap[(mf * 16 + 8) * ASTRIDE + k0]);
                a[mf][2] = __float_as_uint(ap[(mf * 16 + 0) * ASTRIDE + k0 + 4]);
                a[mf][3] = __float_as_uint(ap[(mf * 16 + 8) * ASTRIDE + k0 + 4]);
            }
            #pragma unroll
            for (int nf = 0; nf < 8; nf++) {
                b[nf][0] = __float_as_uint(bp[nf * 8 * ASTRIDE + k0]);
                b[nf][1] = __float_as_uint(bp[nf * 8 * ASTRIDE + k0 + 4]);
            }
            #pragma unroll
            for (int mf = 0; mf < 2; mf++)
                #pragma unroll
                for (int nf = 0; nf < 8; nf++)
                    asm volatile(
                        "mma.sync.aligned.m16n8k8.row.col.f32.tf32.tf32.f32 "
                        "{%0,%1,%2,%3}, {%4,%5,%6,%7}, {%8,%9}, {%0,%1,%2,%3};"
                        : "+f"(acc[mf][nf][0]), "+f"(acc[mf][nf][1]),
                          "+f"(acc[mf][nf][2]), "+f"(acc[mf][nf][3])
                        : "r"(a[mf][0]), "r"(a[mf][1]), "r"(a[mf][2]), "r"(a[mf][3]),
                          "r"(b[nf][0]), "r"(b[nf][1]));
        }
        __syncthreads();
    }

    // epilogue: c0,c1 -> (row, col..col+1); c2,c3 -> (row+8, col..col+1)
    #pragma unroll
    for (int mf = 0; mf < 2; mf++) {
        #pragma unroll
        for (int h = 0; h < 2; h++) {
            int m = m0 + wm + mf * 16 + h * 8 + (lane >> 2);
            float rs = (EPI == 2) ? rowscale[m] : 0.f;
            #pragma unroll
            for (int nf = 0; nf < 8; nf++) {
                int n = n0 + wn + nf * 8 + (lane & 3) * 2;
                size_t idx = (size_t)m * ldc + n;
                float v0 = acc[mf][nf][h * 2 + 0];
                float v1 = acc[mf][nf][h * 2 + 1];
                if (EPI == 0)      { v0 *= alpha; v1 *= alpha; }
                else if (EPI == 2) { v0 = res[idx] + rs * v0; v1 = res[idx + 1] + rs * v1; }
                else if (EPI == 3) { v0 = fmaxf(v0 + bias[n], 0.f); v1 = fmaxf(v1 + bias[n + 1], 0.f); }
                else               { v0 = res[idx] + v0 + bias[n]; v1 = res[idx + 1] + v1 + bias[n + 1]; }
                if (RND) { v0 = tf32r(v0); v1 = tf32r(v1); }
                *(float2*)&Cm[idx] = make_float2(v0, v1);
            }
        }
    }
}

// ================= non-GEMM kernels =================
__global__ void input_stats(const float* __restrict__ x) {
    int gid = blockIdx.x * blockDim.x + threadIdx.x;
    int b = gid >> 12;
    int l = gid & (L_ - 1);
    const float* p = x + (size_t)b * C_ * HW_ + l;
    float s = 0.f, ss = 0.f;
    #pragma unroll 8
    for (int c = 0; c < C_; c++) {
        float v = p[(size_t)c * HW_];
        s += v; ss += v * v;
    }
    float mu = s * (1.f / C_);
    float var = ss * (1.f / C_) - mu * mu;
    g_mu[gid] = mu;
    g_rstd[gid] = rsqrtf(fmaxf(var, 0.f) + EPS_);
}

// x[b,c,l] -> xn[b,l,c], LayerNorm'd, tf32-rounded (gemm operand)
__global__ void transpose_norm(const float* __restrict__ x,
                               const float* __restrict__ gamma,
                               const float* __restrict__ beta) {
    __shared__ float tile[32][33];
    int b  = blockIdx.z;
    int l0 = blockIdx.x * 32;
    int c0 = blockIdx.y * 32;
    int tx = threadIdx.x, ty = threadIdx.y;
    const float* xb = x + (size_t)b * C_ * HW_;
    #pragma unroll
    for (int r = 0; r < 4; r++)
        tile[ty + 8*r][tx] = xb[(size_t)(c0 + ty + 8*r) * HW_ + l0 + tx];
    __syncthreads();
    #pragma unroll
    for (int r = 0; r < 4; r++) {
        int l = l0 + ty + 8*r;
        int c = c0 + tx;
        float mu = g_mu[b*L_ + l];
        float rs = g_rstd[b*L_ + l];
        g_xn[((size_t)(b*L_ + l)) * C_ + c] =
            tf32r((tile[tx][ty + 8*r] - mu) * rs * gamma[c] + beta[c]);
    }
}

// tiled transpose: in [R,C] -> out [C,R], batched over z; optional tf32 round
template<int RND>
__global__ void transpose_mat(const float* __restrict__ in, float* __restrict__ out,
                              int R, int Ccols) {
    __shared__ float tile[32][33];
    size_t bo = (size_t)blockIdx.z * R * Ccols;
    int r0 = blockIdx.y * 32, c0 = blockIdx.x * 32;
    int tx = threadIdx.x, ty = threadIdx.y;
    #pragma unroll
    for (int i = 0; i < 4; i++)
        tile[ty + 8*i][tx] = in[bo + (size_t)(r0 + ty + 8*i) * Ccols + c0 + tx];
    __syncthreads();
    #pragma unroll
    for (int i = 0; i < 4; i++) {
        float v = tile[tx][ty + 8*i];
        out[bo + (size_t)(c0 + ty + 8*i) * R + r0 + tx] = RND ? tf32r(v) : v;
    }
}

__global__ void bcast_tmpl(const float* __restrict__ ti) {
    int i = blockIdx.x * 256 + threadIdx.x;
    g_tmpl[i] = ti[i & (N_*D_ - 1)];
}

__device__ __forceinline__ float block_sum(float v) {
    __shared__ float sh[8];
    __shared__ float tot;
    #pragma unroll
    for (int o = 16; o; o >>= 1) v += __shfl_xor_sync(0xffffffffu, v, o);
    if ((threadIdx.x & 31) == 0) sh[threadIdx.x >> 5] = v;
    __syncthreads();
    if (threadIdx.x == 0) {
        float s = 0.f;
        #pragma unroll
        for (int i = 0; i < 8; i++) s += sh[i];
        tot = s;
    }
    __syncthreads();
    return tot;
}

// row LayerNorm over 1024, output tf32-rounded (gemm operand)
__global__ void ln_rows(const float* __restrict__ in, float* __restrict__ out,
                        const float* __restrict__ gamma, const float* __restrict__ beta) {
    int row = blockIdx.x;
    int t = threadIdx.x;
    float4 v = ((const float4*)(in + (size_t)row * 1024))[t];
    float s = block_sum(v.x + v.y + v.z + v.w);
    float mu = s * (1.f / 1024.f);
    float dx = v.x - mu, dy = v.y - mu, dz = v.z - mu, dw = v.w - mu;
    float ss = block_sum(dx*dx + dy*dy + dz*dz + dw*dw);
    float rs = rsqrtf(ss * (1.f / 1024.f) + EPS_);
    float4 g4 = ((const float4*)gamma)[t];
    float4 b4 = ((const float4*)beta)[t];
    float4 o;
    o.x = tf32r(dx * rs * g4.x + b4.x);
    o.y = tf32r(dy * rs * g4.y + b4.y);
    o.z = tf32r(dz * rs * g4.z + b4.z);
    o.w = tf32r(dw * rs * g4.w + b4.w);
    ((float4*)(out + (size_t)row * 1024))[t] = o;
}

__global__ void softmax_rows(float* __restrict__ p) {
    int warp = threadIdx.x >> 5, lane = threadIdx.x & 31;
    int row = blockIdx.x * 8 + warp;
    float* r = p + (size_t)row * 256;
    float4 a = ((float4*)r)[lane];
    float4 b = ((float4*)r)[32 + lane];
    float mx = fmaxf(fmaxf(fmaxf(a.x, a.y), fmaxf(a.z, a.w)),
                     fmaxf(fmaxf(b.x, b.y), fmaxf(b.z, b.w)));
    #pragma unroll
    for (int o = 16; o; o >>= 1) mx = fmaxf(mx, __shfl_xor_sync(0xffffffffu, mx, o));
    a.x = __expf(a.x - mx); a.y = __expf(a.y - mx);
    a.z = __expf(a.z - mx); a.w = __expf(a.w - mx);
    b.x = __expf(b.x - mx); b.y = __expf(b.y - mx);
    b.z = __expf(b.z - mx); b.w = __expf(b.w - mx);
    float s = a.x + a.y + a.z + a.w + b.x + b.y + b.z + b.w;
    #pragma unroll
    for (int o = 16; o; o >>= 1) s += __shfl_xor_sync(0xffffffffu, s, o);
    float inv = 1.f / s;
    a.x = a.x * inv + 1e-8f; a.y = a.y * inv + 1e-8f;
    a.z = a.z * inv + 1e-8f; a.w = a.w * inv + 1e-8f;
    b.x = b.x * inv + 1e-8f; b.y = b.y * inv + 1e-8f;
    b.z = b.z * inv + 1e-8f; b.w = b.w * inv + 1e-8f;
    ((float4*)r)[lane] = a;
    ((float4*)r)[32 + lane] = b;
}

// 1/colsum from attnT (coalesced row sum over L)
__global__ void colsum_T() {
    int n = blockIdx.x, b = blockIdx.y;
    const float* p = g_attnT + ((size_t)b * N_ + n) * L_;
    float s = 0.f;
    for (int i = threadIdx.x; i < L_; i += 256) s += p[i];
    s = block_sum(s);
    if (threadIdx.x == 0) g_csinv[b * N_ + n] = 1.f / s;
}

__global__ void out_templates_k(float* __restrict__ out) {
    __shared__ float tile[32][33];
    int b = blockIdx.z;
    int n0 = blockIdx.x * 32, d0 = blockIdx.y * 32;
    int tx = threadIdx.x, ty = threadIdx.y;
    const float* tp = g_tmpl + (size_t)b * N_ * D_;
    #pragma unroll
    for (int r = 0; r < 4; r++)
        tile[ty + 8*r][tx] = tp[(size_t)(n0 + ty + 8*r) * D_ + d0 + tx];
    __syncthreads();
    float* op = out + (size_t)b * D_ * N_;
    #pragma unroll
    for (int r = 0; r < 4; r++)
        op[(size_t)(d0 + ty + 8*r) * N_ + n0 + tx] = tile[tx][ty + 8*r];
}

// out_attn[b][n][l] = attn[b][l][n] * csinv[b][n]  (from unrounded attn)
__global__ void out_attn_k(float* __restrict__ out) {
    __shared__ float tile[32][33];
    int b = blockIdx.z;
    int l0 = blockIdx.x * 32, n0 = blockIdx.y * 32;
    int tx = threadIdx.x, ty = threadIdx.y;
    const float* ap = g_attn + (size_t)b * L_ * N_;
    #pragma unroll
    for (int r = 0; r < 4; r++)
        tile[ty + 8*r][tx] = ap[(size_t)(l0 + ty + 8*r) * N_ + n0 + tx];
    __syncthreads();
    float* op = out + (size_t)b * N_ * HW_;
    #pragma unroll
    for (int r = 0; r < 4; r++) {
        int n = n0 + ty + 8*r;
        op[(size_t)n * HW_ + l0 + tx] = tile[tx][ty + 8*r] * g_csinv[b * N_ + n];
    }
}

// ================= launch =================
extern "C" void kernel_launch(void* const* d_in, const int* in_sizes, int n_in,
                              void* d_out, int out_size) {
    const float* x      = (const float*)d_in[0];
    const float* ti     = (const float*)d_in[1];
    const float* Wq     = (const float*)d_in[2];
    const float* Wk     = (const float*)d_in[3];
    const float* Wv     = (const float*)d_in[4];
    const float* lin_g  = (const float*)d_in[5];
    const float* lin_b  = (const float*)d_in[6];
    const float* lt_g   = (const float*)d_in[7];
    const float* lt_b   = (const float*)d_in[8];
    const float* lm_g   = (const float*)d_in[9];
    const float* lm_b   = (const float*)d_in[10];
    const float* W1     = (const float*)d_in[11];
    const float* b1     = (const float*)d_in[12];
    const float* W2     = (const float*)d_in[13];
    const float* b2     = (const float*)d_in[14];
    float* out_t = (float*)d_out;                          // [B, D, N]
    float* out_a = (float*)d_out + (size_t)B_ * D_ * N_;   // [B, N, H, W]

    float *p_xn, *p_k, *p_v, *p_vT, *p_tmpl, *p_t2, *p_q, *p_attn, *p_attnT,
          *p_csinv, *p_h, *p_WqT, *p_WkT, *p_WvT, *p_W1T, *p_W2T;
    cudaGetSymbolAddress((void**)&p_xn, g_xn);
    cudaGetSymbolAddress((void**)&p_k, g_k);
    cudaGetSymbolAddress((void**)&p_v, g_v);
    cudaGetSymbolAddress((void**)&p_vT, g_vT);
    cudaGetSymbolAddress((void**)&p_tmpl, g_tmpl);
    cudaGetSymbolAddress((void**)&p_t2, g_t2);
    cudaGetSymbolAddress((void**)&p_q, g_q);
    cudaGetSymbolAddress((void**)&p_attn, g_attn);
    cudaGetSymbolAddress((void**)&p_attnT, g_attnT);
    cudaGetSymbolAddress((void**)&p_csinv, g_csinv);
    cudaGetSymbolAddress((void**)&p_h, g_h);
    cudaGetSymbolAddress((void**)&p_WqT, g_WqT);
    cudaGetSymbolAddress((void**)&p_WkT, g_WkT);
    cudaGetSymbolAddress((void**)&p_WvT, g_WvT);
    cudaGetSymbolAddress((void**)&p_W1T, g_W1T);
    cudaGetSymbolAddress((void**)&p_W2T, g_W2T);

    const int SMEMSZ = 4 * STAGEF * 4;   // 73728 bytes
    cudaFuncSetAttribute(tgemm<0,1>, cudaFuncAttributeMaxDynamicSharedMemorySize, SMEMSZ);
    cudaFuncSetAttribute(tgemm<0,0>, cudaFuncAttributeMaxDynamicSharedMemorySize, SMEMSZ);
    cudaFuncSetAttribute(tgemm<2,0>, cudaFuncAttributeMaxDynamicSharedMemorySize, SMEMSZ);
    cudaFuncSetAttribute(tgemm<3,1>, cudaFuncAttributeMaxDynamicSharedMemorySize, SMEMSZ);
    cudaFuncSetAttribute(tgemm<4,0>, cudaFuncAttributeMaxDynamicSharedMemorySize, SMEMSZ);

    dim3 tb32(32, 8);

    // weight transposes (W [in,out] -> WT [out,in]); tf32-rounded gemm operands
    transpose_mat<1><<<dim3(D_/32,   D_/32,  1), tb32>>>(Wq, p_WqT, D_,   D_);
    transpose_mat<1><<<dim3(D_/32,   C_/32,  1), tb32>>>(Wk, p_WkT, C_,   D_);
    transpose_mat<1><<<dim3(D_/32,   C_/32,  1), tb32>>>(Wv, p_WvT, C_,   D_);
    transpose_mat<1><<<dim3(MLP_/32, D_/32,  1), tb32>>>(W1, p_W1T, D_,   MLP_);
    transpose_mat<1><<<dim3(D_/32,   MLP_/32,1), tb32>>>(W2, p_W2T, MLP_, D_);

    // input LN + transpose
    input_stats<<<(B_ * L_) / 256, 256>>>(x);
    transpose_norm<<<dim3(HW_ / 32, C_ / 32, B_), tb32>>>(x, lin_g, lin_b);

    // k, v projections
    tgemm<0,1><<<dim3(D_/128, (B_*L_)/128, 1), 256, SMEMSZ>>>(
        p_xn, p_WkT, p_k, C_, D_, 0, 0, 0, nullptr, nullptr, 0, nullptr, 1.f);
    tgemm<0,1><<<dim3(D_/128, (B_*L_)/128, 1), 256, SMEMSZ>>>(
        p_xn, p_WvT, p_v, C_, D_, 0, 0, 0, nullptr, nullptr, 0, nullptr, 1.f);
    transpose_mat<1><<<dim3(D_/32, L_/32, B_), tb32>>>(p_v, p_vT, L_, D_);

    bcast_tmpl<<<(B_ * N_ * D_) / 256, 256>>>(ti);

    for (int it = 0; it < TITER; it++) {
        // t = LN(templates); q = (t @ Wq) * scale
        ln_rows<<<B_ * N_, 256>>>(p_tmpl, p_t2, lt_g, lt_b);
        tgemm<0,1><<<dim3(D_/128, (B_*N_)/128, 1), 256, SMEMSZ>>>(
            p_t2, p_WqT, p_q, D_, D_, 0, 0, 0, nullptr, nullptr, 0, nullptr, SCALE_);

        // logits[b] = k[b] @ q[b]^T
        tgemm<0,0><<<dim3(N_/128, L_/128, B_), 256, SMEMSZ>>>(
            p_k, p_q, p_attn, D_, N_,
            (long long)L_ * D_, (long long)N_ * D_, (long long)L_ * N_,
            nullptr, nullptr, 0, nullptr, 1.f);

        softmax_rows<<<(B_ * L_) / 8, 256>>>(p_attn);
        transpose_mat<1><<<dim3(N_/32, L_/32, B_), tb32>>>(p_attn, p_attnT, L_, N_);
        colsum_T<<<dim3(N_, B_), 256>>>();

        // templates += csinv[n] * (attn^T @ v)
        tgemm<2,0><<<dim3(D_/128, N_/128, B_), 256, SMEMSZ>>>(
            p_attnT, p_vT, p_tmpl, L_, D_,
            (long long)N_ * L_, (long long)D_ * L_, (long long)N_ * D_,
            p_tmpl, p_csinv, N_, nullptr, 1.f);

        // MLP: m = LN(templates); templates += relu(m@W1+b1)@W2 + b2
        ln_rows<<<B_ * N_, 256>>>(p_tmpl, p_t2, lm_g, lm_b);
        tgemm<3,1><<<dim3(MLP_/128, (B_*N_)/128, 1), 256, SMEMSZ>>>(
            p_t2, p_W1T, p_h, D_, MLP_, 0, 0, 0, nullptr, nullptr, 0, b1, 1.f);
        tgemm<4,0><<<dim3(D_/128, (B_*N_)/128, 1), 256, SMEMSZ>>>(
            p_h, p_W2T, p_tmpl, MLP_, D_, 0, 0, 0, p_tmpl, nullptr, 0, b2, 1.f);
    }

    out_templates_k<<<dim3(N_ / 32, D_ / 32, B_), tb32>>>(out_t);
    out_attn_k<<<dim3(L_ / 32, N_ / 32, B_), tb32>>>(out_a);
}

// round 4
// speedup vs baseline: 5.6056x; 1.6463x over previous
#include <cuda_runtime.h>
#include <cuda_fp16.h>
#include <cstdint>

// ---------------- problem constants ----------------
#define B_    8
#define C_    1024       // INPUT_DIM
#define HW_   4096       // H*W
#define L_    4096       // sequence length = H*W
#define D_    1024       // DIM
#define N_    256        // N_SLOTS
#define MLP_  512        // MLP_DIM
#define TITER 6
#define EPS_  1e-5f
#define SCALE_ 0.03125f  // DIM^-0.5

// ---------------- scratch (device globals; no allocation allowed) ----------------
__device__ float g_mu[B_*L_];
__device__ float g_rstd[B_*L_];
__device__ float g_tmpl[B_*N_*D_];                 // fp32 residual stream
__device__ float g_attn [(size_t)B_*L_*N_];        // logits -> attn (fp32)
__device__ float g_cspart[B_*16*N_];
__device__ float g_csinv[B_*N_];

__device__ __half g_xn_h [(size_t)B_*L_*C_];       // 64 MB
__device__ __half g_k_h  [(size_t)B_*L_*D_];       // 64 MB
__device__ __half g_v_h  [(size_t)B_*L_*D_];       // 64 MB
__device__ __half g_vT_h [(size_t)B_*D_*L_];       // 64 MB
__device__ __half g_attnT_h[(size_t)B_*N_*L_];     // 16 MB
__device__ __half g_q_h  [B_*N_*D_];
__device__ __half g_t2_h [B_*N_*D_];
__device__ __half g_h_h  [B_*N_*MLP_];
__device__ __half g_WqT_h[D_*D_];
__device__ __half g_WkT_h[D_*C_];
__device__ __half g_WvT_h[D_*C_];
__device__ __half g_W1T_h[MLP_*D_];
__device__ __half g_W2T_h[D_*MLP_];

// ---------------- helpers ----------------
__device__ __forceinline__ uint32_t smem_u32(const void* p) {
    uint32_t a;
    asm("{ .reg .u64 t; cvta.to.shared.u64 t, %1; cvt.u32.u64 %0, t; }" : "=r"(a) : "l"(p));
    return a;
}
__device__ __forceinline__ void cp16(uint32_t s, const void* g) {
    asm volatile("cp.async.cg.shared.global [%0], [%1], 16;\n" :: "r"(s), "l"(g));
}
#define CP_COMMIT() asm volatile("cp.async.commit_group;\n" ::: "memory")
#define CP_WAIT(N)  asm volatile("cp.async.wait_group %0;\n" :: "n"(N) : "memory")

__device__ __forceinline__ void ldsm4(uint32_t (&r)[4], uint32_t addr) {
    asm volatile("ldmatrix.sync.aligned.m8n8.x4.shared.b16 {%0,%1,%2,%3}, [%4];"
                 : "=r"(r[0]), "=r"(r[1]), "=r"(r[2]), "=r"(r[3]) : "r"(addr));
}
__device__ __forceinline__ void mma16816(float (&c)[4], const uint32_t (&a)[4],
                                         uint32_t b0, uint32_t b1) {
    asm volatile(
        "mma.sync.aligned.m16n8k16.row.col.f32.f16.f16.f32 "
        "{%0,%1,%2,%3}, {%4,%5,%6,%7}, {%8,%9}, {%0,%1,%2,%3};"
        : "+f"(c[0]), "+f"(c[1]), "+f"(c[2]), "+f"(c[3])
        : "r"(a[0]), "r"(a[1]), "r"(a[2]), "r"(a[3]), "r"(b0), "r"(b1));
}

// ================= tensor-core GEMM (fp16 mma.sync m16n8k16) =================
// C[M,N] = epi( A[M,K] @ B[N,K]^T ); A,B K-major __half.
// CTA tile 128x128, KC=64 halves, double-buffered cp.async, 8 warps (4M x 2N),
// warp tile 32x64. SMEM row stride 72 halves (144B) -> ldmatrix conflict-free.
// EPI: 0: alpha*acc   2: res + rowscale[m]*acc   3: relu(acc+bias)   4: res+acc+bias
// OUTH: 1 -> output __half, 0 -> output float
#define KC_ 64
#define SROW 72
#define STAGEH (128 * SROW)   // halves per operand stage

template<int EPI, int OUTH>
__global__ void __launch_bounds__(256, 2)
tgemm(const __half* __restrict__ A, const __half* __restrict__ Bm,
      void* __restrict__ Cv, int K, int ldc,
      long long sA, long long sB, long long sC,
      const float* __restrict__ res, const float* __restrict__ rowscale,
      long long sRow, const float* __restrict__ bias, float alpha) {
    extern __shared__ __half sh[];
    const uint32_t su = smem_u32(sh);

    const int tid  = threadIdx.x;
    const int wid  = tid >> 5;
    const int lane = tid & 31;
    const int wm = (wid >> 1) * 32;
    const int wn = (wid & 1) * 64;

    const int bz = blockIdx.z;
    A  += (size_t)bz * sA;
    Bm += (size_t)bz * sB;
    float*  Cf = (float*)Cv + (OUTH ? 0 : (size_t)bz * sC);
    __half* Ch = (__half*)Cv + (OUTH ? (size_t)bz * sC : 0);
    if (EPI == 2 || EPI == 4) res += (size_t)bz * sC;
    if (EPI == 2) rowscale += (size_t)bz * sRow;

    const int m0 = blockIdx.y * 128;
    const int n0 = blockIdx.x * 128;
    const __half* gA = A + (size_t)m0 * K;
    const __half* gB = Bm + (size_t)n0 * K;

    float acc[2][8][4];
    #pragma unroll
    for (int i = 0; i < 2; i++)
        #pragma unroll
        for (int j = 0; j < 8; j++)
            #pragma unroll
            for (int r = 0; r < 4; r++) acc[i][j][r] = 0.f;

    auto load_chunk = [&](int c) {
        int buf = c & 1;
        uint32_t as = su + (uint32_t)(buf * STAGEH) * 2u;
        uint32_t bs = su + (uint32_t)((2 + buf) * STAGEH) * 2u;
        const __half* ga = gA + c * KC_;
        const __half* gb = gB + c * KC_;
        #pragma unroll
        for (int i = 0; i < 4; i++) {
            int e = tid + i * 256;
            int row = e >> 3;
            int c8 = (e & 7) * 8;              // halves
            uint32_t so = (uint32_t)(row * SROW + c8) * 2u;
            cp16(as + so, ga + (size_t)row * K + c8);
            cp16(bs + so, gb + (size_t)row * K + c8);
        }
        CP_COMMIT();
    };

    const int NC = K / KC_;
    load_chunk(0);

    const int rsel = (lane & 7) + ((lane >> 3) & 1) * 8;  // row within 16
    const int ksel = ((lane >> 4) & 1) * 8;               // k half-offset

    for (int c = 0; c < NC; c++) {
        if (c + 1 < NC) { load_chunk(c + 1); CP_WAIT(1); }
        else            { CP_WAIT(0); }
        __syncthreads();

        int buf = c & 1;
        uint32_t abase = su + (uint32_t)(buf * STAGEH) * 2u;
        uint32_t bbase = su + (uint32_t)((2 + buf) * STAGEH) * 2u;

        #pragma unroll
        for (int ks = 0; ks < 4; ks++) {
            const int k0 = ks * 16 + ksel;
            uint32_t a[2][4];
            #pragma unroll
            for (int mf = 0; mf < 2; mf++)
                ldsm4(a[mf], abase + (uint32_t)((wm + mf * 16 + rsel) * SROW + k0) * 2u);
            uint32_t b[4][4];
            #pragma unroll
            for (int np = 0; np < 4; np++)
                ldsm4(b[np], bbase + (uint32_t)((wn + np * 16 + rsel) * SROW + k0) * 2u);
            #pragma unroll
            for (int mf = 0; mf < 2; mf++)
                #pragma unroll
                for (int nf = 0; nf < 8; nf++)
                    mma16816(acc[mf][nf], a[mf], b[nf >> 1][nf & 1], b[nf >> 1][2 + (nf & 1)]);
        }
        __syncthreads();
    }

    // epilogue: c0,c1 -> (row, col..col+1); c2,c3 -> (row+8, col..col+1)
    #pragma unroll
    for (int mf = 0; mf < 2; mf++) {
        #pragma unroll
        for (int h = 0; h < 2; h++) {
            int m = m0 + wm + mf * 16 + h * 8 + (lane >> 2);
            float rs = (EPI == 2) ? rowscale[m] : 0.f;
            #pragma unroll
            for (int nf = 0; nf < 8; nf++) {
                int n = n0 + wn + nf * 8 + (lane & 3) * 2;
                size_t idx = (size_t)m * ldc + n;
                float v0 = acc[mf][nf][h * 2 + 0];
                float v1 = acc[mf][nf][h * 2 + 1];
                if (EPI == 0)      { v0 *= alpha; v1 *= alpha; }
                else if (EPI == 2) { v0 = res[idx] + rs * v0; v1 = res[idx + 1] + rs * v1; }
                else if (EPI == 3) { v0 = fmaxf(v0 + bias[n], 0.f); v1 = fmaxf(v1 + bias[n + 1], 0.f); }
                else if (EPI == 4) { v0 = res[idx] + v0 + bias[n]; v1 = res[idx + 1] + v1 + bias[n + 1]; }
                if (OUTH) *(__half2*)&Ch[idx] = __floats2half2_rn(v0, v1);
                else      *(float2*)&Cf[idx] = make_float2(v0, v1);
            }
        }
    }
}

// ================= non-GEMM kernels =================
__global__ void input_stats(const float* __restrict__ x) {
    int gid = blockIdx.x * blockDim.x + threadIdx.x;
    int b = gid >> 12;
    int l = gid & (L_ - 1);
    const float* p = x + (size_t)b * C_ * HW_ + l;
    float s = 0.f, ss = 0.f;
    #pragma unroll 8
    for (int c = 0; c < C_; c++) {
        float v = p[(size_t)c * HW_];
        s += v; ss += v * v;
    }
    float mu = s * (1.f / C_);
    float var = ss * (1.f / C_) - mu * mu;
    g_mu[gid] = mu;
    g_rstd[gid] = rsqrtf(fmaxf(var, 0.f) + EPS_);
}

// x[b,c,l] -> xn_h[b,l,c] (LayerNorm, half)
__global__ void transpose_norm(const float* __restrict__ x,
                               const float* __restrict__ gamma,
                               const float* __restrict__ beta) {
    __shared__ float tile[32][33];
    int b  = blockIdx.z;
    int l0 = blockIdx.x * 32;
    int c0 = blockIdx.y * 32;
    int tx = threadIdx.x, ty = threadIdx.y;
    const float* xb = x + (size_t)b * C_ * HW_;
    #pragma unroll
    for (int r = 0; r < 4; r++)
        tile[ty + 8*r][tx] = xb[(size_t)(c0 + ty + 8*r) * HW_ + l0 + tx];
    __syncthreads();
    #pragma unroll
    for (int r = 0; r < 4; r++) {
        int l = l0 + ty + 8*r;
        int c = c0 + tx;
        float mu = g_mu[b*L_ + l];
        float rs = g_rstd[b*L_ + l];
        g_xn_h[((size_t)(b*L_ + l)) * C_ + c] =
            __float2half_rn((tile[tx][ty + 8*r] - mu) * rs * gamma[c] + beta[c]);
    }
}

// tiled transpose: in [R,C] -> out [C,R], batched over z
template<typename Tin, typename Tout>
__global__ void transpose_mat(const Tin* __restrict__ in, Tout* __restrict__ out,
                              int R, int Ccols) {
    __shared__ float tile[32][33];
    size_t bo = (size_t)blockIdx.z * R * Ccols;
    int r0 = blockIdx.y * 32, c0 = blockIdx.x * 32;
    int tx = threadIdx.x, ty = threadIdx.y;
    #pragma unroll
    for (int i = 0; i < 4; i++)
        tile[ty + 8*i][tx] = (float)in[bo + (size_t)(r0 + ty + 8*i) * Ccols + c0 + tx];
    __syncthreads();
    #pragma unroll
    for (int i = 0; i < 4; i++)
        out[bo + (size_t)(c0 + ty + 8*i) * R + r0 + tx] = (Tout)tile[tx][ty + 8*i];
}

__global__ void bcast_tmpl(const float* __restrict__ ti) {
    int i = blockIdx.x * 256 + threadIdx.x;
    g_tmpl[i] = ti[i & (N_*D_ - 1)];
}

__device__ __forceinline__ float block_sum(float v) {
    __shared__ float shm[8];
    __shared__ float tot;
    #pragma unroll
    for (int o = 16; o; o >>= 1) v += __shfl_xor_sync(0xffffffffu, v, o);
    if ((threadIdx.x & 31) == 0) shm[threadIdx.x >> 5] = v;
    __syncthreads();
    if (threadIdx.x == 0) {
        float s = 0.f;
        #pragma unroll
        for (int i = 0; i < 8; i++) s += shm[i];
        tot = s;
    }
    __syncthreads();
    return tot;
}

// row LayerNorm over 1024, half output (gemm operand)
__global__ void ln_rows(const float* __restrict__ in, __half* __restrict__ out,
                        const float* __restrict__ gamma, const float* __restrict__ beta) {
    int row = blockIdx.x;
    int t = threadIdx.x;
    float4 v = ((const float4*)(in + (size_t)row * 1024))[t];
    float s = block_sum(v.x + v.y + v.z + v.w);
    float mu = s * (1.f / 1024.f);
    float dx = v.x - mu, dy = v.y - mu, dz = v.z - mu, dw = v.w - mu;
    float ss = block_sum(dx*dx + dy*dy + dz*dz + dw*dw);
    float rs = rsqrtf(ss * (1.f / 1024.f) + EPS_);
    float4 g4 = ((const float4*)gamma)[t];
    float4 b4 = ((const float4*)beta)[t];
    __half2* orow = (__half2*)(out + (size_t)row * 1024);
    orow[t * 2 + 0] = __floats2half2_rn(dx * rs * g4.x + b4.x, dy * rs * g4.y + b4.y);
    orow[t * 2 + 1] = __floats2half2_rn(dz * rs * g4.z + b4.z, dw * rs * g4.w + b4.w);
}

__global__ void softmax_rows(float* __restrict__ p) {
    int warp = threadIdx.x >> 5, lane = threadIdx.x & 31;
    int row = blockIdx.x * 8 + warp;
    float* r = p + (size_t)row * 256;
    float4 a = ((float4*)r)[lane];
    float4 b = ((float4*)r)[32 + lane];
    float mx = fmaxf(fmaxf(fmaxf(a.x, a.y), fmaxf(a.z, a.w)),
                     fmaxf(fmaxf(b.x, b.y), fmaxf(b.z, b.w)));
    #pragma unroll
    for (int o = 16; o; o >>= 1) mx = fmaxf(mx, __shfl_xor_sync(0xffffffffu, mx, o));
    a.x = __expf(a.x - mx); a.y = __expf(a.y - mx);
    a.z = __expf(a.z - mx); a.w = __expf(a.w - mx);
    b.x = __expf(b.x - mx); b.y = __expf(b.y - mx);
    b.z = __expf(b.z - mx); b.w = __expf(b.w - mx);
    float s = a.x + a.y + a.z + a.w + b.x + b.y + b.z + b.w;
    #pragma unroll
    for (int o = 16; o; o >>= 1) s += __shfl_xor_sync(0xffffffffu, s, o);
    float inv = 1.f / s;
    a.x = a.x * inv + 1e-8f; a.y = a.y * inv + 1e-8f;
    a.z = a.z * inv + 1e-8f; a.w = a.w * inv + 1e-8f;
    b.x = b.x * inv + 1e-8f; b.y = b.y * inv + 1e-8f;
    b.z = b.z * inv + 1e-8f; b.w = b.w * inv + 1e-8f;
    ((float4*)r)[lane] = a;
    ((float4*)r)[32 + lane] = b;
}

// column-sum over L (two stages, coalesced over n) -> 1/colsum
__global__ void colsum_part() {
    int chunk = blockIdx.x, b = blockIdx.y, n = threadIdx.x;
    const float* p = g_attn + (size_t)b * L_ * N_ + (size_t)chunk * 256 * N_ + n;
    float s = 0.f;
    #pragma unroll 8
    for (int l = 0; l < 256; l++) s += p[(size_t)l * N_];
    g_cspart[(b * 16 + chunk) * N_ + n] = s;
}
__global__ void colsum_fin() {
    int b = blockIdx.x, n = threadIdx.x;
    float s = 0.f;
    #pragma unroll
    for (int i = 0; i < 16; i++) s += g_cspart[(b * 16 + i) * N_ + n];
    g_csinv[b * N_ + n] = 1.f / s;
}

__global__ void out_templates_k(float* __restrict__ out) {
    __shared__ float tile[32][33];
    int b = blockIdx.z;
    int n0 = blockIdx.x * 32, d0 = blockIdx.y * 32;
    int tx = threadIdx.x, ty = threadIdx.y;
    const float* tp = g_tmpl + (size_t)b * N_ * D_;
    #pragma unroll
    for (int r = 0; r < 4; r++)
        tile[ty + 8*r][tx] = tp[(size_t)(n0 + ty + 8*r) * D_ + d0 + tx];
    __syncthreads();
    float* op = out + (size_t)b * D_ * N_;
    #pragma unroll
    for (int r = 0; r < 4; r++)
        op[(size_t)(d0 + ty + 8*r) * N_ + n0 + tx] = tile[tx][ty + 8*r];
}

// out_attn[b][n][l] = attn[b][l][n] * csinv[b][n]
__global__ void out_attn_k(float* __restrict__ out) {
    __shared__ float tile[32][33];
    int b = blockIdx.z;
    int l0 = blockIdx.x * 32, n0 = blockIdx.y * 32;
    int tx = threadIdx.x, ty = threadIdx.y;
    const float* ap = g_attn + (size_t)b * L_ * N_;
    #pragma unroll
    for (int r = 0; r < 4; r++)
        tile[ty + 8*r][tx] = ap[(size_t)(l0 + ty + 8*r) * N_ + n0 + tx];
    __syncthreads();
    float* op = out + (size_t)b * N_ * HW_;
    #pragma unroll
    for (int r = 0; r < 4; r++) {
        int n = n0 + ty + 8*r;
        op[(size_t)n * HW_ + l0 + tx] = tile[tx][ty + 8*r] * g_csinv[b * N_ + n];
    }
}

// ================= launch =================
extern "C" void kernel_launch(void* const* d_in, const int* in_sizes, int n_in,
                              void* d_out, int out_size) {
    const float* x      = (const float*)d_in[0];
    const float* ti     = (const float*)d_in[1];
    const float* Wq     = (const float*)d_in[2];
    const float* Wk     = (const float*)d_in[3];
    const float* Wv     = (const float*)d_in[4];
    const float* lin_g  = (const float*)d_in[5];
    const float* lin_b  = (const float*)d_in[6];
    const float* lt_g   = (const float*)d_in[7];
    const float* lt_b   = (const float*)d_in[8];
    const float* lm_g   = (const float*)d_in[9];
    const float* lm_b   = (const float*)d_in[10];
    const float* W1     = (const float*)d_in[11];
    const float* b1     = (const float*)d_in[12];
    const float* W2     = (const float*)d_in[13];
    const float* b2     = (const float*)d_in[14];
    float* out_t = (float*)d_out;                          // [B, D, N]
    float* out_a = (float*)d_out + (size_t)B_ * D_ * N_;   // [B, N, H, W]

    float *p_tmpl, *p_attn;
    __half *p_xn, *p_k, *p_v, *p_vT, *p_attnT, *p_q, *p_t2, *p_h;
    __half *p_WqT, *p_WkT, *p_WvT, *p_W1T, *p_W2T;
    float *p_csinv;
    cudaGetSymbolAddress((void**)&p_tmpl, g_tmpl);
    cudaGetSymbolAddress((void**)&p_attn, g_attn);
    cudaGetSymbolAddress((void**)&p_csinv, g_csinv);
    cudaGetSymbolAddress((void**)&p_xn, g_xn_h);
    cudaGetSymbolAddress((void**)&p_k, g_k_h);
    cudaGetSymbolAddress((void**)&p_v, g_v_h);
    cudaGetSymbolAddress((void**)&p_vT, g_vT_h);
    cudaGetSymbolAddress((void**)&p_attnT, g_attnT_h);
    cudaGetSymbolAddress((void**)&p_q, g_q_h);
    cudaGetSymbolAddress((void**)&p_t2, g_t2_h);
    cudaGetSymbolAddress((void**)&p_h, g_h_h);
    cudaGetSymbolAddress((void**)&p_WqT, g_WqT_h);
    cudaGetSymbolAddress((void**)&p_WkT, g_WkT_h);
    cudaGetSymbolAddress((void**)&p_WvT, g_WvT_h);
    cudaGetSymbolAddress((void**)&p_W1T, g_W1T_h);
    cudaGetSymbolAddress((void**)&p_W2T, g_W2T_h);

    const int SMEMSZ = 4 * STAGEH * 2;   // 73728 bytes
    cudaFuncSetAttribute(tgemm<0,1>, cudaFuncAttributeMaxDynamicSharedMemorySize, SMEMSZ);
    cudaFuncSetAttribute(tgemm<0,0>, cudaFuncAttributeMaxDynamicSharedMemorySize, SMEMSZ);
    cudaFuncSetAttribute(tgemm<2,0>, cudaFuncAttributeMaxDynamicSharedMemorySize, SMEMSZ);
    cudaFuncSetAttribute(tgemm<3,1>, cudaFuncAttributeMaxDynamicSharedMemorySize, SMEMSZ);
    cudaFuncSetAttribute(tgemm<4,0>, cudaFuncAttributeMaxDynamicSharedMemorySize, SMEMSZ);

    dim3 tb32(32, 8);

    // weight transposes (W [in,out] -> WT [out,in]), fp32 -> half
    transpose_mat<float,__half><<<dim3(D_/32,   D_/32,  1), tb32>>>(Wq, p_WqT, D_,   D_);
    transpose_mat<float,__half><<<dim3(D_/32,   C_/32,  1), tb32>>>(Wk, p_WkT, C_,   D_);
    transpose_mat<float,__half><<<dim3(D_/32,   C_/32,  1), tb32>>>(Wv, p_WvT, C_,   D_);
    transpose_mat<float,__half><<<dim3(MLP_/32, D_/32,  1), tb32>>>(W1, p_W1T, D_,   MLP_);
    transpose_mat<float,__half><<<dim3(D_/32,   MLP_/32,1), tb32>>>(W2, p_W2T, MLP_, D_);

    // input LN + transpose
    input_stats<<<(B_ * L_) / 256, 256>>>(x);
    transpose_norm<<<dim3(HW_ / 32, C_ / 32, B_), tb32>>>(x, lin_g, lin_b);

    // k, v projections (half out)
    tgemm<0,1><<<dim3(D_/128, (B_*L_)/128, 1), 256, SMEMSZ>>>(
        p_xn, p_WkT, p_k, C_, D_, 0, 0, 0, nullptr, nullptr, 0, nullptr, 1.f);
    tgemm<0,1><<<dim3(D_/128, (B_*L_)/128, 1), 256, SMEMSZ>>>(
        p_xn, p_WvT, p_v, C_, D_, 0, 0, 0, nullptr, nullptr, 0, nullptr, 1.f);
    transpose_mat<__half,__half><<<dim3(D_/32, L_/32, B_), tb32>>>(p_v, p_vT, L_, D_);

    bcast_tmpl<<<(B_ * N_ * D_) / 256, 256>>>(ti);

    for (int it = 0; it < TITER; it++) {
        // t = LN(templates); q = (t @ Wq) * scale  (half out)
        ln_rows<<<B_ * N_, 256>>>(p_tmpl, p_t2, lt_g, lt_b);
        tgemm<0,1><<<dim3(D_/128, (B_*N_)/128, 1), 256, SMEMSZ>>>(
            p_t2, p_WqT, p_q, D_, D_, 0, 0, 0, nullptr, nullptr, 0, nullptr, SCALE_);

        // logits[b] = k[b] @ q[b]^T  (float out)
        tgemm<0,0><<<dim3(N_/128, L_/128, B_), 256, SMEMSZ>>>(
            p_k, p_q, p_attn, D_, N_,
            (long long)L_ * D_, (long long)N_ * D_, (long long)L_ * N_,
            nullptr, nullptr, 0, nullptr, 1.f);

        softmax_rows<<<(B_ * L_) / 8, 256>>>(p_attn);
        transpose_mat<float,__half><<<dim3(N_/32, L_/32, B_), tb32>>>(p_attn, p_attnT, L_, N_);
        colsum_part<<<dim3(16, B_), 256>>>();
        colsum_fin<<<B_, 256>>>();

        // templates += csinv[n] * (attn^T @ v)  (float out)
        tgemm<2,0><<<dim3(D_/128, N_/128, B_), 256, SMEMSZ>>>(
            p_attnT, p_vT, p_tmpl, L_, D_,
            (long long)N_ * L_, (long long)D_ * L_, (long long)N_ * D_,
            p_tmpl, p_csinv, N_, nullptr, 1.f);

        // MLP: m = LN(templates); templates += relu(m@W1+b1)@W2 + b2
        ln_rows<<<B_ * N_, 256>>>(p_tmpl, p_t2, lm_g, lm_b);
        tgemm<3,1><<<dim3(MLP_/128, (B_*N_)/128, 1), 256, SMEMSZ>>>(
            p_t2, p_W1T, p_h, D_, MLP_, 0, 0, 0, nullptr, nullptr, 0, b1, 1.f);
        tgemm<4,0><<<dim3(D_/128, (B_*N_)/128, 1), 256, SMEMSZ>>>(
            p_h, p_W2T, p_tmpl, MLP_, D_, 0, 0, 0, p_tmpl, nullptr, 0, b2, 1.f);
    }

    out_templates_k<<<dim3(N_ / 32, D_ / 32, B_), tb32>>>(out_t);
    out_attn_k<<<dim3(L_ / 32, N_ / 32, B_), tb32>>>(out_a);
}

// round 7
// speedup vs baseline: 5.9217x; 1.0564x over previous
#include <cuda_runtime.h>
#include <cuda_fp16.h>
#include <cstdint>

// ---------------- problem constants ----------------
#define B_    8
#define C_    1024       // INPUT_DIM
#define HW_   4096       // H*W
#define L_    4096       // sequence length = H*W
#define D_    1024       // DIM
#define N_    256        // N_SLOTS
#define MLP_  512        // MLP_DIM
#define TITER 6
#define EPS_  1e-5f
#define SCALE_ 0.03125f  // DIM^-0.5
#define SPLK  4          // split-K factor for update GEMM

// ---------------- scratch (device globals; no allocation allowed) ----------------
__device__ float g_mu[B_*L_];
__device__ float g_rstd[B_*L_];
__device__ float g_tmpl[B_*N_*D_];                 // fp32 residual stream
__device__ float g_attn [(size_t)B_*L_*N_];        // logits; last iter: attn (fp32)
__device__ float g_cspart[B_*128*N_];
__device__ float g_csinv[B_*N_];
__device__ float g_part[(size_t)SPLK*B_*N_*D_];    // split-K partials (32 MB)

__device__ __half g_xn_h [(size_t)B_*L_*C_];       // 64 MB
__device__ __half g_k_h  [(size_t)B_*L_*D_];       // 64 MB
__device__ __half g_vT_h [(size_t)B_*D_*L_];       // 64 MB
__device__ __half g_attnT_h[(size_t)B_*N_*L_];     // 16 MB
__device__ __half g_q_h  [B_*N_*D_];
__device__ __half g_t2_h [B_*N_*D_];
__device__ __half g_h_h  [B_*N_*MLP_];
__device__ __half g_WqT_h[D_*D_];
__device__ __half g_WkT_h[D_*C_];
__device__ __half g_WvT_h[D_*C_];
__device__ __half g_W1T_h[MLP_*D_];
__device__ __half g_W2T_h[D_*MLP_];

// ---------------- helpers ----------------
__device__ __forceinline__ uint32_t smem_u32(const void* p) {
    uint32_t a;
    asm("{ .reg .u64 t; cvta.to.shared.u64 t, %1; cvt.u32.u64 %0, t; }" : "=r"(a) : "l"(p));
    return a;
}
__device__ __forceinline__ void cp16(uint32_t s, const void* g) {
    asm volatile("cp.async.cg.shared.global [%0], [%1], 16;\n" :: "r"(s), "l"(g));
}
#define CP_COMMIT() asm volatile("cp.async.commit_group;\n" ::: "memory")
#define CP_WAIT(N)  asm volatile("cp.async.wait_group %0;\n" :: "n"(N) : "memory")

__device__ __forceinline__ void ldsm4(uint32_t (&r)[4], uint32_t addr) {
    asm volatile("ldmatrix.sync.aligned.m8n8.x4.shared.b16 {%0,%1,%2,%3}, [%4];"
                 : "=r"(r[0]), "=r"(r[1]), "=r"(r[2]), "=r"(r[3]) : "r"(addr));
}
__device__ __forceinline__ void mma16816(float (&c)[4], const uint32_t (&a)[4],
                                         uint32_t b0, uint32_t b1) {
    asm volatile(
        "mma.sync.aligned.m16n8k16.row.col.f32.f16.f16.f32 "
        "{%0,%1,%2,%3}, {%4,%5,%6,%7}, {%8,%9}, {%0,%1,%2,%3};"
        : "+f"(c[0]), "+f"(c[1]), "+f"(c[2]), "+f"(c[3])
        : "r"(a[0]), "r"(a[1]), "r"(a[2]), "r"(a[3]), "r"(b0), "r"(b1));
}

// ================= tensor-core GEMM (fp16 mma.sync m16n8k16) =================
// C[M,N] = epi( A[M,K] @ B[N,K]^T ); A,B K-major __half with leading dim Kld,
// loop length Klen. CTA tile 128x128, KC=64, double-buffered cp.async,
// 8 warps (4M x 2N), warp tile 32x64. SROW=72 halves -> ldmatrix conflict-free.
// EPI: 0: alpha*acc   3: relu(acc+bias)   4: res+acc+bias
// OUTH: 1 -> __half out, 0 -> float out
// SPLITK: grid.z = batches*SPLITK; partial z stored at Cv + z*sC (float)
// OUTT: transposed half output (v^T): batch b=m0>>12, row n0+r, col (m0&4095)+c
#define KC_ 64
#define SROW 72
#define STAGEH (128 * SROW)   // halves per operand stage

template<int EPI, int OUTH, int SPLITK, int OUTT>
__global__ void __launch_bounds__(256, 2)
tgemm(const __half* __restrict__ A, const __half* __restrict__ Bm,
      void* __restrict__ Cv, int Kld, int Klen, int ldc,
      long long sA, long long sB, long long sC,
      const float* __restrict__ res, const float* __restrict__ bias, float alpha) {
    extern __shared__ __half sh[];
    const uint32_t su = smem_u32(sh);

    const int tid  = threadIdx.x;
    const int wid  = tid >> 5;
    const int lane = tid & 31;
    const int wm = (wid >> 1) * 32;
    const int wn = (wid & 1) * 64;

    const int z = blockIdx.z;
    const int bz = (SPLITK > 1) ? z / SPLITK : z;
    const int sk = (SPLITK > 1) ? z % SPLITK : 0;
    A  += (size_t)bz * sA + (size_t)sk * Klen;
    Bm += (size_t)bz * sB + (size_t)sk * Klen;
    float*  Cf;
    __half* Ch = (__half*)Cv;
    if (SPLITK > 1) Cf = (float*)Cv + (size_t)z * sC;
    else            Cf = (float*)Cv + (OUTH ? 0 : (size_t)bz * sC);
    if (OUTH && !OUTT) Ch = (__half*)Cv + (size_t)bz * sC;
    if (EPI == 4) res += (size_t)bz * sC;

    const int m0 = blockIdx.y * 128;
    const int n0 = blockIdx.x * 128;
    const __half* gA = A + (size_t)m0 * Kld;
    const __half* gB = Bm + (size_t)n0 * Kld;

    float acc[2][8][4];
    #pragma unroll
    for (int i = 0; i < 2; i++)
        #pragma unroll
        for (int j = 0; j < 8; j++)
            #pragma unroll
            for (int r = 0; r < 4; r++) acc[i][j][r] = 0.f;

    auto load_chunk = [&](int c) {
        int buf = c & 1;
        uint32_t as = su + (uint32_t)(buf * STAGEH) * 2u;
        uint32_t bs = su + (uint32_t)((2 + buf) * STAGEH) * 2u;
        const __half* ga = gA + c * KC_;
        const __half* gb = gB + c * KC_;
        #pragma unroll
        for (int i = 0; i < 4; i++) {
            int e = tid + i * 256;
            int row = e >> 3;
            int c8 = (e & 7) * 8;
            uint32_t so = (uint32_t)(row * SROW + c8) * 2u;
            cp16(as + so, ga + (size_t)row * Kld + c8);
            cp16(bs + so, gb + (size_t)row * Kld + c8);
        }
        CP_COMMIT();
    };

    const int NC = Klen / KC_;
    load_chunk(0);

    const int rsel = (lane & 7) + ((lane >> 3) & 1) * 8;
    const int ksel = ((lane >> 4) & 1) * 8;

    for (int c = 0; c < NC; c++) {
        if (c + 1 < NC) { load_chunk(c + 1); CP_WAIT(1); }
        else            { CP_WAIT(0); }
        __syncthreads();

        int buf = c & 1;
        uint32_t abase = su + (uint32_t)(buf * STAGEH) * 2u;
        uint32_t bbase = su + (uint32_t)((2 + buf) * STAGEH) * 2u;

        #pragma unroll
        for (int ks = 0; ks < 4; ks++) {
            const int k0 = ks * 16 + ksel;
            uint32_t a[2][4];
            #pragma unroll
            for (int mf = 0; mf < 2; mf++)
                ldsm4(a[mf], abase + (uint32_t)((wm + mf * 16 + rsel) * SROW + k0) * 2u);
            uint32_t b[4][4];
            #pragma unroll
            for (int np = 0; np < 4; np++)
                ldsm4(b[np], bbase + (uint32_t)((wn + np * 16 + rsel) * SROW + k0) * 2u);
            #pragma unroll
            for (int mf = 0; mf < 2; mf++)
                #pragma unroll
                for (int nf = 0; nf < 8; nf++)
                    mma16816(acc[mf][nf], a[mf], b[nf >> 1][nf & 1], b[nf >> 1][2 + (nf & 1)]);
        }
        __syncthreads();
    }

    if (OUTT) {
        // stage transposed half tile in smem, then coalesced global write of v^T
        __half* stg = sh;
        #pragma unroll
        for (int mf = 0; mf < 2; mf++)
            #pragma unroll
            for (int h = 0; h < 2; h++) {
                int ml = wm + mf * 16 + h * 8 + (lane >> 2);
                #pragma unroll
                for (int nf = 0; nf < 8; nf++) {
                    int nl = wn + nf * 8 + (lane & 3) * 2;
                    stg[nl * 136 + ml]       = __float2half_rn(acc[mf][nf][h * 2 + 0]);
                    stg[(nl + 1) * 136 + ml] = __float2half_rn(acc[mf][nf][h * 2 + 1]);
                }
            }
        __syncthreads();
        int b = m0 >> 12;
        int l0 = m0 & (L_ - 1);
        __half* dst = Ch + (size_t)b * D_ * L_ + (size_t)n0 * L_ + l0;
        int r = tid >> 1, c0 = (tid & 1) * 64;
        const uint4* s4 = (const uint4*)(stg + r * 136 + c0);
        uint4* d4 = (uint4*)(dst + (size_t)r * L_ + c0);
        #pragma unroll
        for (int i = 0; i < 8; i++) d4[i] = s4[i];
        return;
    }

    #pragma unroll
    for (int mf = 0; mf < 2; mf++) {
        #pragma unroll
        for (int h = 0; h < 2; h++) {
            int m = m0 + wm + mf * 16 + h * 8 + (lane >> 2);
            #pragma unroll
            for (int nf = 0; nf < 8; nf++) {
                int n = n0 + wn + nf * 8 + (lane & 3) * 2;
                size_t idx = (size_t)m * ldc + n;
                float v0 = acc[mf][nf][h * 2 + 0];
                float v1 = acc[mf][nf][h * 2 + 1];
                if (EPI == 0)      { v0 *= alpha; v1 *= alpha; }
                else if (EPI == 3) { v0 = fmaxf(v0 + bias[n], 0.f); v1 = fmaxf(v1 + bias[n + 1], 0.f); }
                else if (EPI == 4) { v0 = res[idx] + v0 + bias[n]; v1 = res[idx + 1] + v1 + bias[n + 1]; }
                if (OUTH) *(__half2*)&Ch[idx] = __floats2half2_rn(v0, v1);
                else      *(float2*)&Cf[idx] = make_float2(v0, v1);
            }
        }
    }
}

// ---------------- split-K reduce: templates += csinv[n] * sum_s part[s] ----------------
__global__ void reduce_update() {
    size_t e = (size_t)blockIdx.x * 256 + threadIdx.x;   // over B*N*D
    int b = (int)(e >> 18);                              // N_*D_ = 2^18
    int n = (int)((e >> 10) & (N_ - 1));
    size_t off = e & ((size_t)N_ * D_ - 1);
    float s = 0.f;
    #pragma unroll
    for (int sk = 0; sk < SPLK; sk++)
        s += g_part[((size_t)(b * SPLK + sk)) * N_ * D_ + off];
    g_tmpl[e] += g_csinv[b * N_ + n] * s;
}

// ================= non-GEMM kernels =================
__global__ void input_stats(const float* __restrict__ x) {
    int gid = blockIdx.x * blockDim.x + threadIdx.x;
    int b = gid >> 12;
    int l = gid & (L_ - 1);
    const float* p = x + (size_t)b * C_ * HW_ + l;
    float s = 0.f, ss = 0.f;
    #pragma unroll 8
    for (int c = 0; c < C_; c++) {
        float v = p[(size_t)c * HW_];
        s += v; ss += v * v;
    }
    float mu = s * (1.f / C_);
    float var = ss * (1.f / C_) - mu * mu;
    g_mu[gid] = mu;
    g_rstd[gid] = rsqrtf(fmaxf(var, 0.f) + EPS_);
}

__global__ void transpose_norm(const float* __restrict__ x,
                               const float* __restrict__ gamma,
                               const float* __restrict__ beta) {
    __shared__ float tile[32][33];
    int b  = blockIdx.z;
    int l0 = blockIdx.x * 32;
    int c0 = blockIdx.y * 32;
    int tx = threadIdx.x, ty = threadIdx.y;
    const float* xb = x + (size_t)b * C_ * HW_;
    #pragma unroll
    for (int r = 0; r < 4; r++)
        tile[ty + 8*r][tx] = xb[(size_t)(c0 + ty + 8*r) * HW_ + l0 + tx];
    __syncthreads();
    #pragma unroll
    for (int r = 0; r < 4; r++) {
        int l = l0 + ty + 8*r;
        int c = c0 + tx;
        float mu = g_mu[b*L_ + l];
        float rs = g_rstd[b*L_ + l];
        g_xn_h[((size_t)(b*L_ + l)) * C_ + c] =
            __float2half_rn((tile[tx][ty + 8*r] - mu) * rs * gamma[c] + beta[c]);
    }
}

// fp32 -> half tiled transpose (weights, one-time)
__global__ void transpose_w(const float* __restrict__ in, __half* __restrict__ out,
                            int R, int Ccols) {
    __shared__ float tile[32][33];
    int r0 = blockIdx.y * 32, c0 = blockIdx.x * 32;
    int tx = threadIdx.x, ty = threadIdx.y;
    #pragma unroll
    for (int i = 0; i < 4; i++)
        tile[ty + 8*i][tx] = in[(size_t)(r0 + ty + 8*i) * Ccols + c0 + tx];
    __syncthreads();
    #pragma unroll
    for (int i = 0; i < 4; i++)
        out[(size_t)(c0 + ty + 8*i) * R + r0 + tx] = __float2half_rn(tile[tx][ty + 8*i]);
}

__global__ void bcast_tmpl(const float* __restrict__ ti) {
    int i = blockIdx.x * 256 + threadIdx.x;
    g_tmpl[i] = ti[i & (N_*D_ - 1)];
}

__device__ __forceinline__ float block_sum(float v) {
    __shared__ float shm[8];
    __shared__ float tot;
    #pragma unroll
    for (int o = 16; o; o >>= 1) v += __shfl_xor_sync(0xffffffffu, v, o);
    if ((threadIdx.x & 31) == 0) shm[threadIdx.x >> 5] = v;
    __syncthreads();
    if (threadIdx.x == 0) {
        float s = 0.f;
        #pragma unroll
        for (int i = 0; i < 8; i++) s += shm[i];
        tot = s;
    }
    __syncthreads();
    return tot;
}

__global__ void ln_rows(const float* __restrict__ in, __half* __restrict__ out,
                        const float* __restrict__ gamma, const float* __restrict__ beta) {
    int row = blockIdx.x;
    int t = threadIdx.x;
    float4 v = ((const float4*)(in + (size_t)row * 1024))[t];
    float s = block_sum(v.x + v.y + v.z + v.w);
    float mu = s * (1.f / 1024.f);
    float dx = v.x - mu, dy = v.y - mu, dz = v.z - mu, dw = v.w - mu;
    float ss = block_sum(dx*dx + dy*dy + dz*dz + dw*dw);
    float rs = rsqrtf(ss * (1.f / 1024.f) + EPS_);
    float4 g4 = ((const float4*)gamma)[t];
    float4 b4 = ((const float4*)beta)[t];
    __half2* orow = (__half2*)(out + (size_t)row * 1024);
    orow[t * 2 + 0] = __floats2half2_rn(dx * rs * g4.x + b4.x, dy * rs * g4.y + b4.y);
    orow[t * 2 + 1] = __floats2half2_rn(dz * rs * g4.z + b4.z, dw * rs * g4.w + b4.w);
}

// -------- fused softmax + transpose + colsum-partials (+ optional fp32 writeback) --------
// grid (L/32, B), block 256. Each warp softmaxes 4 rows; smem transposed tile;
// writes half attnT[n][l], per-block colsum partials; LAST: normalized fp32 attn in-place.
template<int LAST>
__global__ void softmax_fuse() {
    __shared__ float T[256][33];
    int tidx = threadIdx.x;
    int b = blockIdx.y, l0 = blockIdx.x * 32;
    int warp = tidx >> 5, lane = tidx & 31;
    float* base = g_attn + (size_t)b * L_ * N_ + (size_t)l0 * N_;
    #pragma unroll
    for (int rr = 0; rr < 4; rr++) {
        int ll = warp * 4 + rr;
        float* r = base + (size_t)ll * N_;
        float4 a = ((float4*)r)[lane];
        float4 c = ((float4*)r)[32 + lane];
        float mx = fmaxf(fmaxf(fmaxf(a.x, a.y), fmaxf(a.z, a.w)),
                         fmaxf(fmaxf(c.x, c.y), fmaxf(c.z, c.w)));
        #pragma unroll
        for (int o = 16; o; o >>= 1) mx = fmaxf(mx, __shfl_xor_sync(0xffffffffu, mx, o));
        a.x = __expf(a.x - mx); a.y = __expf(a.y - mx);
        a.z = __expf(a.z - mx); a.w = __expf(a.w - mx);
        c.x = __expf(c.x - mx); c.y = __expf(c.y - mx);
        c.z = __expf(c.z - mx); c.w = __expf(c.w - mx);
        float s = a.x + a.y + a.z + a.w + c.x + c.y + c.z + c.w;
        #pragma unroll
        for (int o = 16; o; o >>= 1) s += __shfl_xor_sync(0xffffffffu, s, o);
        float inv = 1.f / s;
        T[4*lane + 0][ll] = a.x * inv + 1e-8f;
        T[4*lane + 1][ll] = a.y * inv + 1e-8f;
        T[4*lane + 2][ll] = a.z * inv + 1e-8f;
        T[4*lane + 3][ll] = a.w * inv + 1e-8f;
        T[128 + 4*lane + 0][ll] = c.x * inv + 1e-8f;
        T[128 + 4*lane + 1][ll] = c.y * inv + 1e-8f;
        T[128 + 4*lane + 2][ll] = c.z * inv + 1e-8f;
        T[128 + 4*lane + 3][ll] = c.w * inv + 1e-8f;
    }
    __syncthreads();
    {   // colsum partial for this 32-row chunk
        float s = 0.f;
        #pragma unroll
        for (int j = 0; j < 32; j++) s += T[tidx][j];
        g_cspart[((size_t)b * 128 + blockIdx.x) * N_ + tidx] = s;
    }
    {   // half attnT[n][l0+lane]
        __half* at = g_attnT_h + (size_t)b * N_ * L_ + l0;
        #pragma unroll
        for (int i = 0; i < 32; i++) {
            int n = warp * 32 + i;
            at[(size_t)n * L_ + lane] = __float2half_rn(T[n][lane]);
        }
    }
    if (LAST) {
        #pragma unroll
        for (int i = 0; i < 32; i++)
            base[(size_t)i * N_ + tidx] = T[tidx][i];
    }
}

__global__ void colsum_fin() {
    int b = blockIdx.x, n = threadIdx.x;
    float s = 0.f;
    #pragma unroll 8
    for (int i = 0; i < 128; i++) s += g_cspart[((size_t)b * 128 + i) * N_ + n];
    g_csinv[b * N_ + n] = 1.f / s;
}

__global__ void out_templates_k(float* __restrict__ out) {
    __shared__ float tile[32][33];
    int b = blockIdx.z;
    int n0 = blockIdx.x * 32, d0 = blockIdx.y * 32;
    int tx = threadIdx.x, ty = threadIdx.y;
    const float* tp = g_tmpl + (size_t)b * N_ * D_;
    #pragma unroll
    for (int r = 0; r < 4; r++)
        tile[ty + 8*r][tx] = tp[(size_t)(n0 + ty + 8*r) * D_ + d0 + tx];
    __syncthreads();
    float* op = out + (size_t)b * D_ * N_;
    #pragma unroll
    for (int r = 0; r < 4; r++)
        op[(size_t)(d0 + ty + 8*r) * N_ + n0 + tx] = tile[tx][ty + 8*r];
}

// out_attn[b][n][l] = attn[b][l][n] * csinv[b][n]
__global__ void out_attn_k(float* __restrict__ out) {
    __shared__ float tile[32][33];
    int b = blockIdx.z;
    int l0 = blockIdx.x * 32, n0 = blockIdx.y * 32;
    int tx = threadIdx.x, ty = threadIdx.y;
    const float* ap = g_attn + (size_t)b * L_ * N_;
    #pragma unroll
    for (int r = 0; r < 4; r++)
        tile[ty + 8*r][tx] = ap[(size_t)(l0 + ty + 8*r) * N_ + n0 + tx];
    __syncthreads();
    float* op = out + (size_t)b * N_ * HW_;
    #pragma unroll
    for (int r = 0; r < 4; r++) {
        int n = n0 + ty + 8*r;
        op[(size_t)n * HW_ + l0 + tx] = tile[tx][ty + 8*r] * g_csinv[b * N_ + n];
    }
}

// ================= launch =================
extern "C" void kernel_launch(void* const* d_in, const int* in_sizes, int n_in,
                              void* d_out, int out_size) {
    const float* x      = (const float*)d_in[0];
    const float* ti     = (const float*)d_in[1];
    const float* Wq     = (const float*)d_in[2];
    const float* Wk     = (const float*)d_in[3];
    const float* Wv     = (const float*)d_in[4];
    const float* lin_g  = (const float*)d_in[5];
    const float* lin_b  = (const float*)d_in[6];
    const float* lt_g   = (const float*)d_in[7];
    const float* lt_b   = (const float*)d_in[8];
    const float* lm_g   = (const float*)d_in[9];
    const float* lm_b   = (const float*)d_in[10];
    const float* W1     = (const float*)d_in[11];
    const float* b1     = (const float*)d_in[12];
    const float* W2     = (const float*)d_in[13];
    const float* b2     = (const float*)d_in[14];
    float* out_t = (float*)d_out;                          // [B, D, N]
    float* out_a = (float*)d_out + (size_t)B_ * D_ * N_;   // [B, N, H, W]

    float *p_tmpl, *p_attn, *p_part;
    __half *p_xn, *p_k, *p_vT, *p_attnT, *p_q, *p_t2, *p_h;
    __half *p_WqT, *p_WkT, *p_WvT, *p_W1T, *p_W2T;
    cudaGetSymbolAddress((void**)&p_tmpl, g_tmpl);
    cudaGetSymbolAddress((void**)&p_attn, g_attn);
    cudaGetSymbolAddress((void**)&p_part, g_part);
    cudaGetSymbolAddress((void**)&p_xn, g_xn_h);
    cudaGetSymbolAddress((void**)&p_k, g_k_h);
    cudaGetSymbolAddress((void**)&p_vT, g_vT_h);
    cudaGetSymbolAddress((void**)&p_attnT, g_attnT_h);
    cudaGetSymbolAddress((void**)&p_q, g_q_h);
    cudaGetSymbolAddress((void**)&p_t2, g_t2_h);
    cudaGetSymbolAddress((void**)&p_h, g_h_h);
    cudaGetSymbolAddress((void**)&p_WqT, g_WqT_h);
    cudaGetSymbolAddress((void**)&p_WkT, g_WkT_h);
    cudaGetSymbolAddress((void**)&p_WvT, g_WvT_h);
    cudaGetSymbolAddress((void**)&p_W1T, g_W1T_h);
    cudaGetSymbolAddress((void**)&p_W2T, g_W2T_h);

    const int SMEMSZ = 4 * STAGEH * 2;   // 73728 bytes
    cudaFuncSetAttribute(tgemm<0,1,1,0>, cudaFuncAttributeMaxDynamicSharedMemorySize, SMEMSZ);
    cudaFuncSetAttribute(tgemm<0,0,1,0>, cudaFuncAttributeMaxDynamicSharedMemorySize, SMEMSZ);
    cudaFuncSetAttribute(tgemm<0,0,1,1>, cudaFuncAttributeMaxDynamicSharedMemorySize, SMEMSZ);
    cudaFuncSetAttribute(tgemm<0,0,SPLK,0>, cudaFuncAttributeMaxDynamicSharedMemorySize, SMEMSZ);
    cudaFuncSetAttribute(tgemm<3,1,1,0>, cudaFuncAttributeMaxDynamicSharedMemorySize, SMEMSZ);
    cudaFuncSetAttribute(tgemm<4,0,1,0>, cudaFuncAttributeMaxDynamicSharedMemorySize, SMEMSZ);

    dim3 tb32(32, 8);

    // weight transposes (one-time)
    transpose_w<<<dim3(D_/32,   D_/32),   tb32>>>(Wq, p_WqT, D_,   D_);
    transpose_w<<<dim3(D_/32,   C_/32),   tb32>>>(Wk, p_WkT, C_,   D_);
    transpose_w<<<dim3(D_/32,   C_/32),   tb32>>>(Wv, p_WvT, C_,   D_);
    transpose_w<<<dim3(MLP_/32, D_/32),   tb32>>>(W1, p_W1T, D_,   MLP_);
    transpose_w<<<dim3(D_/32,   MLP_/32), tb32>>>(W2, p_W2T, MLP_, D_);

    // input LN + transpose
    input_stats<<<(B_ * L_) / 256, 256>>>(x);
    transpose_norm<<<dim3(HW_ / 32, C_ / 32, B_), tb32>>>(x, lin_g, lin_b);

    // k projection (half out); v projection writes v^T directly (OUTT)
    tgemm<0,1,1,0><<<dim3(D_/128, (B_*L_)/128, 1), 256, SMEMSZ>>>(
        p_xn, p_WkT, p_k, C_, C_, D_, 0, 0, 0, nullptr, nullptr, 1.f);
    tgemm<0,0,1,1><<<dim3(D_/128, (B_*L_)/128, 1), 256, SMEMSZ>>>(
        p_xn, p_WvT, p_vT, C_, C_, L_, 0, 0, 0, nullptr, nullptr, 1.f);

    bcast_tmpl<<<(B_ * N_ * D_) / 256, 256>>>(ti);

    for (int it = 0; it < TITER; it++) {
        // t = LN(templates); q = (t @ Wq) * scale  (half out)
        ln_rows<<<B_ * N_, 256>>>(p_tmpl, p_t2, lt_g, lt_b);
        tgemm<0,1,1,0><<<dim3(D_/128, (B_*N_)/128, 1), 256, SMEMSZ>>>(
            p_t2, p_WqT, p_q, D_, D_, D_, 0, 0, 0, nullptr, nullptr, SCALE_);

        // logits[b] = k[b] @ q[b]^T  (float out)
        tgemm<0,0,1,0><<<dim3(N_/128, L_/128, B_), 256, SMEMSZ>>>(
            p_k, p_q, p_attn, D_, D_, N_,
            (long long)L_ * D_, (long long)N_ * D_, (long long)L_ * N_,
            nullptr, nullptr, 1.f);

        // fused softmax + transpose + colsum partials
        if (it == TITER - 1) softmax_fuse<1><<<dim3(L_/32, B_), 256>>>();
        else                 softmax_fuse<0><<<dim3(L_/32, B_), 256>>>();
        colsum_fin<<<B_, 256>>>();

        // update: split-K partials of attn^T @ v, then fused reduce+residual
        tgemm<0,0,SPLK,0><<<dim3(D_/128, N_/128, B_ * SPLK), 256, SMEMSZ>>>(
            p_attnT, p_vT, p_part, L_, L_ / SPLK, D_,
            (long long)N_ * L_, (long long)D_ * L_, (long long)N_ * D_,
            nullptr, nullptr, 1.f);
        reduce_update<<<(B_ * N_ * D_) / 256, 256>>>();

        // MLP: m = LN(templates); templates += relu(m@W1+b1)@W2 + b2
        ln_rows<<<B_ * N_, 256>>>(p_tmpl, p_t2, lm_g, lm_b);
        tgemm<3,1,1,0><<<dim3(MLP_/128, (B_*N_)/128, 1), 256, SMEMSZ>>>(
            p_t2, p_W1T, p_h, D_, D_, MLP_, 0, 0, 0, nullptr, b1, 1.f);
        tgemm<4,0,1,0><<<dim3(D_/128, (B_*N_)/128, 1), 256, SMEMSZ>>>(
            p_h, p_W2T, p_tmpl, MLP_, MLP_, D_, 0, 0, 0, p_tmpl, b2, 1.f);
    }

    out_templates_k<<<dim3(N_ / 32, D_ / 32, B_), tb32>>>(out_t);
    out_attn_k<<<dim3(L_ / 32, N_ / 32, B_), tb32>>>(out_a);
}

// round 8
// speedup vs baseline: 6.0179x; 1.0162x over previous
#include <cuda_runtime.h>
#include <cuda_fp16.h>
#include <cstdint>

// ---------------- problem constants ----------------
#define B_    8
#define C_    1024       // INPUT_DIM
#define HW_   4096       // H*W
#define L_    4096       // sequence length = H*W
#define D_    1024       // DIM
#define N_    256        // N_SLOTS
#define MLP_  512        // MLP_DIM
#define TITER 6
#define EPS_  1e-5f
#define SCALE_ 0.03125f  // DIM^-0.5
#define SPLK  4          // split-K factor for update GEMM

// ---------------- scratch (device globals; no allocation allowed) ----------------
__device__ float g_mu[B_*L_];
__device__ float g_rstd[B_*L_];
__device__ float g_tmpl[B_*N_*D_];                 // fp32 residual stream
__device__ float g_attn [(size_t)B_*L_*N_];        // last iter: attn (fp32)
__device__ float g_cspart[B_*32*N_];
__device__ float g_csinv[B_*N_];
__device__ float g_part[(size_t)SPLK*B_*N_*D_];    // split-K partials (32 MB)

__device__ __half g_xn_h [(size_t)B_*L_*C_];       // 64 MB
__device__ __half g_k_h  [(size_t)B_*L_*D_];       // 64 MB
__device__ __half g_vT_h [(size_t)B_*D_*L_];       // 64 MB
__device__ __half g_attnT_h[(size_t)B_*N_*L_];     // 16 MB
__device__ __half g_q_h  [B_*N_*D_];
__device__ __half g_t2_h [B_*N_*D_];
__device__ __half g_h_h  [B_*N_*MLP_];
__device__ __half g_WqT_h[D_*D_];
__device__ __half g_WkT_h[D_*C_];
__device__ __half g_WvT_h[D_*C_];
__device__ __half g_W1T_h[MLP_*D_];
__device__ __half g_W2T_h[D_*MLP_];

// ---------------- helpers ----------------
__device__ __forceinline__ uint32_t smem_u32(const void* p) {
    uint32_t a;
    asm("{ .reg .u64 t; cvta.to.shared.u64 t, %1; cvt.u32.u64 %0, t; }" : "=r"(a) : "l"(p));
    return a;
}
__device__ __forceinline__ void cp16(uint32_t s, const void* g) {
    asm volatile("cp.async.cg.shared.global [%0], [%1], 16;\n" :: "r"(s), "l"(g));
}
#define CP_COMMIT() asm volatile("cp.async.commit_group;\n" ::: "memory")
#define CP_WAIT(N)  asm volatile("cp.async.wait_group %0;\n" :: "n"(N) : "memory")

__device__ __forceinline__ void ldsm4(uint32_t (&r)[4], uint32_t addr) {
    asm volatile("ldmatrix.sync.aligned.m8n8.x4.shared.b16 {%0,%1,%2,%3}, [%4];"
                 : "=r"(r[0]), "=r"(r[1]), "=r"(r[2]), "=r"(r[3]) : "r"(addr));
}
__device__ __forceinline__ void mma16816(float (&c)[4], const uint32_t (&a)[4],
                                         uint32_t b0, uint32_t b1) {
    asm volatile(
        "mma.sync.aligned.m16n8k16.row.col.f32.f16.f16.f32 "
        "{%0,%1,%2,%3}, {%4,%5,%6,%7}, {%8,%9}, {%0,%1,%2,%3};"
        : "+f"(c[0]), "+f"(c[1]), "+f"(c[2]), "+f"(c[3])
        : "r"(a[0]), "r"(a[1]), "r"(a[2]), "r"(a[3]), "r"(b0), "r"(b1));
}

// ================= generic tensor-core GEMM (fp16 mma.sync m16n8k16) =================
#define KC_ 64
#define SROW 72
#define STAGEH (128 * SROW)   // halves per operand stage

template<int EPI, int OUTH, int SPLITK, int OUTT>
__global__ void __launch_bounds__(256, 2)
tgemm(const __half* __restrict__ A, const __half* __restrict__ Bm,
      void* __restrict__ Cv, int Kld, int Klen, int ldc,
      long long sA, long long sB, long long sC,
      const float* __restrict__ res, const float* __restrict__ bias, float alpha) {
    extern __shared__ __half sh[];
    const uint32_t su = smem_u32(sh);

    const int tid  = threadIdx.x;
    const int wid  = tid >> 5;
    const int lane = tid & 31;
    const int wm = (wid >> 1) * 32;
    const int wn = (wid & 1) * 64;

    const int z = blockIdx.z;
    const int bz = (SPLITK > 1) ? z / SPLITK : z;
    const int sk = (SPLITK > 1) ? z % SPLITK : 0;
    A  += (size_t)bz * sA + (size_t)sk * Klen;
    Bm += (size_t)bz * sB + (size_t)sk * Klen;
    float*  Cf;
    __half* Ch = (__half*)Cv;
    if (SPLITK > 1) Cf = (float*)Cv + (size_t)z * sC;
    else            Cf = (float*)Cv + (OUTH ? 0 : (size_t)bz * sC);
    if (OUTH && !OUTT) Ch = (__half*)Cv + (size_t)bz * sC;
    if (EPI == 4) res += (size_t)bz * sC;

    const int m0 = blockIdx.y * 128;
    const int n0 = blockIdx.x * 128;
    const __half* gA = A + (size_t)m0 * Kld;
    const __half* gB = Bm + (size_t)n0 * Kld;

    float acc[2][8][4];
    #pragma unroll
    for (int i = 0; i < 2; i++)
        #pragma unroll
        for (int j = 0; j < 8; j++)
            #pragma unroll
            for (int r = 0; r < 4; r++) acc[i][j][r] = 0.f;

    auto load_chunk = [&](int c) {
        int buf = c & 1;
        uint32_t as = su + (uint32_t)(buf * STAGEH) * 2u;
        uint32_t bs = su + (uint32_t)((2 + buf) * STAGEH) * 2u;
        const __half* ga = gA + c * KC_;
        const __half* gb = gB + c * KC_;
        #pragma unroll
        for (int i = 0; i < 4; i++) {
            int e = tid + i * 256;
            int row = e >> 3;
            int c8 = (e & 7) * 8;
            uint32_t so = (uint32_t)(row * SROW + c8) * 2u;
            cp16(as + so, ga + (size_t)row * Kld + c8);
            cp16(bs + so, gb + (size_t)row * Kld + c8);
        }
        CP_COMMIT();
    };

    const int NC = Klen / KC_;
    load_chunk(0);

    const int rsel = (lane & 7) + ((lane >> 3) & 1) * 8;
    const int ksel = ((lane >> 4) & 1) * 8;

    for (int c = 0; c < NC; c++) {
        if (c + 1 < NC) { load_chunk(c + 1); CP_WAIT(1); }
        else            { CP_WAIT(0); }
        __syncthreads();

        int buf = c & 1;
        uint32_t abase = su + (uint32_t)(buf * STAGEH) * 2u;
        uint32_t bbase = su + (uint32_t)((2 + buf) * STAGEH) * 2u;

        #pragma unroll
        for (int ks = 0; ks < 4; ks++) {
            const int k0 = ks * 16 + ksel;
            uint32_t a[2][4];
            #pragma unroll
            for (int mf = 0; mf < 2; mf++)
                ldsm4(a[mf], abase + (uint32_t)((wm + mf * 16 + rsel) * SROW + k0) * 2u);
            uint32_t b[4][4];
            #pragma unroll
            for (int np = 0; np < 4; np++)
                ldsm4(b[np], bbase + (uint32_t)((wn + np * 16 + rsel) * SROW + k0) * 2u);
            #pragma unroll
            for (int mf = 0; mf < 2; mf++)
                #pragma unroll
                for (int nf = 0; nf < 8; nf++)
                    mma16816(acc[mf][nf], a[mf], b[nf >> 1][nf & 1], b[nf >> 1][2 + (nf & 1)]);
        }
        __syncthreads();
    }

    if (OUTT) {
        __half* stg = sh;
        #pragma unroll
        for (int mf = 0; mf < 2; mf++)
            #pragma unroll
            for (int h = 0; h < 2; h++) {
                int ml = wm + mf * 16 + h * 8 + (lane >> 2);
                #pragma unroll
                for (int nf = 0; nf < 8; nf++) {
                    int nl = wn + nf * 8 + (lane & 3) * 2;
                    stg[nl * 136 + ml]       = __float2half_rn(acc[mf][nf][h * 2 + 0]);
                    stg[(nl + 1) * 136 + ml] = __float2half_rn(acc[mf][nf][h * 2 + 1]);
                }
            }
        __syncthreads();
        int b = m0 >> 12;
        int l0 = m0 & (L_ - 1);
        __half* dst = Ch + (size_t)b * D_ * L_ + (size_t)n0 * L_ + l0;
        int r = tid >> 1, c0 = (tid & 1) * 64;
        const uint4* s4 = (const uint4*)(stg + r * 136 + c0);
        uint4* d4 = (uint4*)(dst + (size_t)r * L_ + c0);
        #pragma unroll
        for (int i = 0; i < 8; i++) d4[i] = s4[i];
        return;
    }

    #pragma unroll
    for (int mf = 0; mf < 2; mf++) {
        #pragma unroll
        for (int h = 0; h < 2; h++) {
            int m = m0 + wm + mf * 16 + h * 8 + (lane >> 2);
            #pragma unroll
            for (int nf = 0; nf < 8; nf++) {
                int n = n0 + wn + nf * 8 + (lane & 3) * 2;
                size_t idx = (size_t)m * ldc + n;
                float v0 = acc[mf][nf][h * 2 + 0];
                float v1 = acc[mf][nf][h * 2 + 1];
                if (EPI == 0)      { v0 *= alpha; v1 *= alpha; }
                else if (EPI == 3) { v0 = fmaxf(v0 + bias[n], 0.f); v1 = fmaxf(v1 + bias[n + 1], 0.f); }
                else if (EPI == 4) { v0 = res[idx] + v0 + bias[n]; v1 = res[idx + 1] + v1 + bias[n + 1]; }
                if (OUTH) *(__half2*)&Ch[idx] = __floats2half2_rn(v0, v1);
                else      *(float2*)&Cf[idx] = make_float2(v0, v1);
            }
        }
    }
}

// ================= fused logits GEMM + softmax + attnT + colsum =================
// Tile M=128 x N=256 (full slot dim), KC=32, grid (1, L/128, B).
// Epilogue: softmax over N in registers, +1e-8, half attnT (transposed),
// per-CTA colsum partials, fp32 attn on LAST iter.
#define ATROW 40
#define ATSTAGE (384 * ATROW)    // halves per stage (A 128 rows + B 256 rows)

template<int LAST>
__global__ void __launch_bounds__(256, 1)
attn_gemm() {
    extern __shared__ __half sh[];
    char* sc = (char*)sh;
    const uint32_t su = smem_u32(sh);
    const int tid = threadIdx.x, wid = tid >> 5, lane = tid & 31;
    const int wm = (wid >> 1) * 32, wn = (wid & 1) * 128;
    const int b = blockIdx.z, m0 = blockIdx.y * 128;
    const __half* gA = g_k_h + ((size_t)b * L_ + m0) * D_;
    const __half* gB = g_q_h + (size_t)b * N_ * D_;

    float acc[2][16][4];
    #pragma unroll
    for (int i = 0; i < 2; i++)
        #pragma unroll
        for (int j = 0; j < 16; j++)
            #pragma unroll
            for (int r = 0; r < 4; r++) acc[i][j][r] = 0.f;

    auto load_chunk = [&](int c) {
        uint32_t st = su + (uint32_t)((c & 1) * ATSTAGE) * 2u;
        #pragma unroll
        for (int i = 0; i < 2; i++) {           // A: 128 rows x 32 halves
            int e = tid + i * 256;
            int row = e >> 2, qq = (e & 3) * 8;
            cp16(st + (uint32_t)(row * ATROW + qq) * 2u, gA + (size_t)row * D_ + c * 32 + qq);
        }
        #pragma unroll
        for (int i = 0; i < 4; i++) {           // B: 256 rows x 32 halves
            int e = tid + i * 256;
            int row = e >> 2, qq = (e & 3) * 8;
            cp16(st + (uint32_t)((128 + row) * ATROW + qq) * 2u, gB + (size_t)row * D_ + c * 32 + qq);
        }
        CP_COMMIT();
    };

    const int NC = D_ / 32;
    load_chunk(0);
    const int rsel = (lane & 7) + ((lane >> 3) & 1) * 8;
    const int ksel = ((lane >> 4) & 1) * 8;

    for (int c = 0; c < NC; c++) {
        if (c + 1 < NC) { load_chunk(c + 1); CP_WAIT(1); }
        else            { CP_WAIT(0); }
        __syncthreads();
        uint32_t abase = su + (uint32_t)((c & 1) * ATSTAGE) * 2u;
        uint32_t bbase = abase + (uint32_t)(128 * ATROW) * 2u;
        #pragma unroll
        for (int ks = 0; ks < 2; ks++) {
            const int k0 = ks * 16 + ksel;
            uint32_t a[2][4];
            #pragma unroll
            for (int mf = 0; mf < 2; mf++)
                ldsm4(a[mf], abase + (uint32_t)((wm + mf * 16 + rsel) * ATROW + k0) * 2u);
            uint32_t bf[8][4];
            #pragma unroll
            for (int np = 0; np < 8; np++)
                ldsm4(bf[np], bbase + (uint32_t)((wn + np * 16 + rsel) * ATROW + k0) * 2u);
            #pragma unroll
            for (int mf = 0; mf < 2; mf++)
                #pragma unroll
                for (int nf = 0; nf < 16; nf++)
                    mma16816(acc[mf][nf], a[mf], bf[nf >> 1][nf & 1], bf[nf >> 1][2 + (nf & 1)]);
        }
        __syncthreads();
    }

    // ---- softmax epilogue ----
    __half* stg = sh;                           // [256 cols][136] transposed halves
    float* redv = (float*)(sc + 69632);         // 256 floats
    const int nwh = (wid & 1);
    float mx4[4], inv4[4];

    #pragma unroll
    for (int r = 0; r < 4; r++) {               // row max (warp-local 128 cols)
        int mf = r >> 1, hh = r & 1;
        float m = -1e30f;
        #pragma unroll
        for (int nf = 0; nf < 16; nf++)
            m = fmaxf(m, fmaxf(acc[mf][nf][hh * 2], acc[mf][nf][hh * 2 + 1]));
        m = fmaxf(m, __shfl_xor_sync(0xffffffffu, m, 1));
        m = fmaxf(m, __shfl_xor_sync(0xffffffffu, m, 2));
        if ((lane & 3) == 0)
            redv[nwh * 128 + wm + mf * 16 + hh * 8 + (lane >> 2)] = m;
    }
    __syncthreads();
    #pragma unroll
    for (int r = 0; r < 4; r++) {
        int rowl = wm + (r >> 1) * 16 + (r & 1) * 8 + (lane >> 2);
        mx4[r] = fmaxf(redv[rowl], redv[128 + rowl]);
    }
    __syncthreads();
    #pragma unroll
    for (int r = 0; r < 4; r++) {               // exp + row sum
        int mf = r >> 1, hh = r & 1;
        float s = 0.f;
        #pragma unroll
        for (int nf = 0; nf < 16; nf++) {
            float e0 = __expf(acc[mf][nf][hh * 2]     - mx4[r]);
            float e1 = __expf(acc[mf][nf][hh * 2 + 1] - mx4[r]);
            acc[mf][nf][hh * 2] = e0; acc[mf][nf][hh * 2 + 1] = e1;
            s += e0 + e1;
        }
        s += __shfl_xor_sync(0xffffffffu, s, 1);
        s += __shfl_xor_sync(0xffffffffu, s, 2);
        if ((lane & 3) == 0)
            redv[nwh * 128 + wm + mf * 16 + hh * 8 + (lane >> 2)] = s;
    }
    __syncthreads();
    #pragma unroll
    for (int r = 0; r < 4; r++) {
        int rowl = wm + (r >> 1) * 16 + (r & 1) * 8 + (lane >> 2);
        inv4[r] = 1.f / (redv[rowl] + redv[128 + rowl]);
    }
    // normalize, +1e-8, stage transposed half; LAST -> fp32 attn
    #pragma unroll
    for (int r = 0; r < 4; r++) {
        int mf = r >> 1, hh = r & 1;
        int rowl = wm + mf * 16 + hh * 8 + (lane >> 2);
        #pragma unroll
        for (int nf = 0; nf < 16; nf++) {
            float p0 = acc[mf][nf][hh * 2]     * inv4[r] + 1e-8f;
            float p1 = acc[mf][nf][hh * 2 + 1] * inv4[r] + 1e-8f;
            int col = wn + nf * 8 + (lane & 3) * 2;
            stg[col * 136 + rowl]       = __float2half_rn(p0);
            stg[(col + 1) * 136 + rowl] = __float2half_rn(p1);
            if (LAST)
                *(float2*)&g_attn[((size_t)b * L_ + m0 + rowl) * N_ + col] = make_float2(p0, p1);
        }
    }
    __syncthreads();
    // colsum + coalesced attnT write (thread t owns slot n = t)
    {
        float cs = 0.f;
        const uint4* s4 = (const uint4*)(stg + tid * 136);
        uint4* d4 = (uint4*)(g_attnT_h + ((size_t)b * N_ + tid) * L_ + m0);
        #pragma unroll
        for (int j = 0; j < 16; j++) {
            uint4 u = s4[j];
            d4[j] = u;
            const __half2* hp = (const __half2*)&u;
            #pragma unroll
            for (int t = 0; t < 4; t++) {
                float2 f = __half22float2(hp[t]);
                cs += f.x + f.y;
            }
        }
        g_cspart[((size_t)b * 32 + blockIdx.y) * N_ + tid] = cs;
    }
}

// ---------------- block reduction ----------------
__device__ __forceinline__ float block_sum(float v) {
    __shared__ float shm[8];
    __shared__ float tot;
    #pragma unroll
    for (int o = 16; o; o >>= 1) v += __shfl_xor_sync(0xffffffffu, v, o);
    if ((threadIdx.x & 31) == 0) shm[threadIdx.x >> 5] = v;
    __syncthreads();
    if (threadIdx.x == 0) {
        float s = 0.f;
        #pragma unroll
        for (int i = 0; i < 8; i++) s += shm[i];
        tot = s;
    }
    __syncthreads();
    return tot;
}

// ---- fused: colsum finalize + split-K reduce + residual + LayerNorm(lm) -> t2 half ----
__global__ void update_ln(const float* __restrict__ gam, const float* __restrict__ bet) {
    int row = blockIdx.x;                 // b*N + n
    int b = row >> 8, n = row & (N_ - 1);
    int t = threadIdx.x;
    float cp = (t < 32) ? g_cspart[((size_t)b * 32 + t) * N_ + n] : 0.f;
    float tot = block_sum(cp);
    float inv = 1.f / tot;
    if (t == 0) g_csinv[row] = inv;
    size_t eb = (size_t)row * 1024 + t * 4;
    float4 u = *(const float4*)&g_tmpl[eb];
    float4 ps = make_float4(0.f, 0.f, 0.f, 0.f);
    #pragma unroll
    for (int sk = 0; sk < SPLK; sk++) {
        float4 pp = *(const float4*)&g_part[((size_t)(b * SPLK + sk) * N_ + n) * 1024 + t * 4];
        ps.x += pp.x; ps.y += pp.y; ps.z += pp.z; ps.w += pp.w;
    }
    u.x += inv * ps.x; u.y += inv * ps.y; u.z += inv * ps.z; u.w += inv * ps.w;
    float s1 = block_sum(u.x + u.y + u.z + u.w);
    float mu = s1 * (1.f / 1024.f);
    float dx = u.x - mu, dy = u.y - mu, dz = u.z - mu, dw = u.w - mu;
    float ss = block_sum(dx*dx + dy*dy + dz*dz + dw*dw);
    float rs = rsqrtf(ss * (1.f / 1024.f) + EPS_);
    *(float4*)&g_tmpl[eb] = u;
    float4 g4 = ((const float4*)gam)[t];
    float4 b4 = ((const float4*)bet)[t];
    __half2* o = (__half2*)(g_t2_h + (size_t)row * 1024);
    o[t * 2 + 0] = __floats2half2_rn(dx * rs * g4.x + b4.x, dy * rs * g4.y + b4.y);
    o[t * 2 + 1] = __floats2half2_rn(dz * rs * g4.z + b4.z, dw * rs * g4.w + b4.w);
}

// ================= non-GEMM kernels =================
__global__ void input_stats(const float* __restrict__ x) {
    int gid = blockIdx.x * blockDim.x + threadIdx.x;
    int b = gid >> 12;
    int l = gid & (L_ - 1);
    const float* p = x + (size_t)b * C_ * HW_ + l;
    float s = 0.f, ss = 0.f;
    #pragma unroll 8
    for (int c = 0; c < C_; c++) {
        float v = p[(size_t)c * HW_];
        s += v; ss += v * v;
    }
    float mu = s * (1.f / C_);
    float var = ss * (1.f / C_) - mu * mu;
    g_mu[gid] = mu;
    g_rstd[gid] = rsqrtf(fmaxf(var, 0.f) + EPS_);
}

__global__ void transpose_norm(const float* __restrict__ x,
                               const float* __restrict__ gamma,
                               const float* __restrict__ beta) {
    __shared__ float tile[32][33];
    int b  = blockIdx.z;
    int l0 = blockIdx.x * 32;
    int c0 = blockIdx.y * 32;
    int tx = threadIdx.x, ty = threadIdx.y;
    const float* xb = x + (size_t)b * C_ * HW_;
    #pragma unroll
    for (int r = 0; r < 4; r++)
        tile[ty + 8*r][tx] = xb[(size_t)(c0 + ty + 8*r) * HW_ + l0 + tx];
    __syncthreads();
    #pragma unroll
    for (int r = 0; r < 4; r++) {
        int l = l0 + ty + 8*r;
        int c = c0 + tx;
        float mu = g_mu[b*L_ + l];
        float rs = g_rstd[b*L_ + l];
        g_xn_h[((size_t)(b*L_ + l)) * C_ + c] =
            __float2half_rn((tile[tx][ty + 8*r] - mu) * rs * gamma[c] + beta[c]);
    }
}

__global__ void transpose_w(const float* __restrict__ in, __half* __restrict__ out,
                            int R, int Ccols) {
    __shared__ float tile[32][33];
    int r0 = blockIdx.y * 32, c0 = blockIdx.x * 32;
    int tx = threadIdx.x, ty = threadIdx.y;
    #pragma unroll
    for (int i = 0; i < 4; i++)
        tile[ty + 8*i][tx] = in[(size_t)(r0 + ty + 8*i) * Ccols + c0 + tx];
    __syncthreads();
    #pragma unroll
    for (int i = 0; i < 4; i++)
        out[(size_t)(c0 + ty + 8*i) * R + r0 + tx] = __float2half_rn(tile[tx][ty + 8*i]);
}

__global__ void bcast_tmpl(const float* __restrict__ ti) {
    int i = blockIdx.x * 256 + threadIdx.x;
    g_tmpl[i] = ti[i & (N_*D_ - 1)];
}

__global__ void ln_rows(const float* __restrict__ in, __half* __restrict__ out,
                        const float* __restrict__ gamma, const float* __restrict__ beta) {
    int row = blockIdx.x;
    int t = threadIdx.x;
    float4 v = ((const float4*)(in + (size_t)row * 1024))[t];
    float s = block_sum(v.x + v.y + v.z + v.w);
    float mu = s * (1.f / 1024.f);
    float dx = v.x - mu, dy = v.y - mu, dz = v.z - mu, dw = v.w - mu;
    float ss = block_sum(dx*dx + dy*dy + dz*dz + dw*dw);
    float rs = rsqrtf(ss * (1.f / 1024.f) + EPS_);
    float4 g4 = ((const float4*)gamma)[t];
    float4 b4 = ((const float4*)beta)[t];
    __half2* orow = (__half2*)(out + (size_t)row * 1024);
    orow[t * 2 + 0] = __floats2half2_rn(dx * rs * g4.x + b4.x, dy * rs * g4.y + b4.y);
    orow[t * 2 + 1] = __floats2half2_rn(dz * rs * g4.z + b4.z, dw * rs * g4.w + b4.w);
}

__global__ void out_templates_k(float* __restrict__ out) {
    __shared__ float tile[32][33];
    int b = blockIdx.z;
    int n0 = blockIdx.x * 32, d0 = blockIdx.y * 32;
    int tx = threadIdx.x, ty = threadIdx.y;
    const float* tp = g_tmpl + (size_t)b * N_ * D_;
    #pragma unroll
    for (int r = 0; r < 4; r++)
        tile[ty + 8*r][tx] = tp[(size_t)(n0 + ty + 8*r) * D_ + d0 + tx];
    __syncthreads();
    float* op = out + (size_t)b * D_ * N_;
    #pragma unroll
    for (int r = 0; r < 4; r++)
        op[(size_t)(d0 + ty + 8*r) * N_ + n0 + tx] = tile[tx][ty + 8*r];
}

__global__ void out_attn_k(float* __restrict__ out) {
    __shared__ float tile[32][33];
    int b = blockIdx.z;
    int l0 = blockIdx.x * 32, n0 = blockIdx.y * 32;
    int tx = threadIdx.x, ty = threadIdx.y;
    const float* ap = g_attn + (size_t)b * L_ * N_;
    #pragma unroll
    for (int r = 0; r < 4; r++)
        tile[ty + 8*r][tx] = ap[(size_t)(l0 + ty + 8*r) * N_ + n0 + tx];
    __syncthreads();
    float* op = out + (size_t)b * N_ * HW_;
    #pragma unroll
    for (int r = 0; r < 4; r++) {
        int n = n0 + ty + 8*r;
        op[(size_t)n * HW_ + l0 + tx] = tile[tx][ty + 8*r] * g_csinv[b * N_ + n];
    }
}

// ================= launch =================
extern "C" void kernel_launch(void* const* d_in, const int* in_sizes, int n_in,
                              void* d_out, int out_size) {
    const float* x      = (const float*)d_in[0];
    const float* ti     = (const float*)d_in[1];
    const float* Wq     = (const float*)d_in[2];
    const float* Wk     = (const float*)d_in[3];
    const float* Wv     = (const float*)d_in[4];
    const float* lin_g  = (const float*)d_in[5];
    const float* lin_b  = (const float*)d_in[6];
    const float* lt_g   = (const float*)d_in[7];
    const float* lt_b   = (const float*)d_in[8];
    const float* lm_g   = (const float*)d_in[9];
    const float* lm_b   = (const float*)d_in[10];
    const float* W1     = (const float*)d_in[11];
    const float* b1     = (const float*)d_in[12];
    const float* W2     = (const float*)d_in[13];
    const float* b2     = (const float*)d_in[14];
    float* out_t = (float*)d_out;                          // [B, D, N]
    float* out_a = (float*)d_out + (size_t)B_ * D_ * N_;   // [B, N, H, W]

    float *p_tmpl, *p_part;
    __half *p_xn, *p_k, *p_vT, *p_attnT, *p_q, *p_t2, *p_h;
    __half *p_WqT, *p_WkT, *p_WvT, *p_W1T, *p_W2T;
    cudaGetSymbolAddress((void**)&p_tmpl, g_tmpl);
    cudaGetSymbolAddress((void**)&p_part, g_part);
    cudaGetSymbolAddress((void**)&p_xn, g_xn_h);
    cudaGetSymbolAddress((void**)&p_k, g_k_h);
    cudaGetSymbolAddress((void**)&p_vT, g_vT_h);
    cudaGetSymbolAddress((void**)&p_attnT, g_attnT_h);
    cudaGetSymbolAddress((void**)&p_q, g_q_h);
    cudaGetSymbolAddress((void**)&p_t2, g_t2_h);
    cudaGetSymbolAddress((void**)&p_h, g_h_h);
    cudaGetSymbolAddress((void**)&p_WqT, g_WqT_h);
    cudaGetSymbolAddress((void**)&p_WkT, g_WkT_h);
    cudaGetSymbolAddress((void**)&p_WvT, g_WvT_h);
    cudaGetSymbolAddress((void**)&p_W1T, g_W1T_h);
    cudaGetSymbolAddress((void**)&p_W2T, g_W2T_h);

    const int SMEMSZ = 4 * STAGEH * 2;   // 73728 bytes (covers attn_gemm: 70656)
    cudaFuncSetAttribute(tgemm<0,1,1,0>, cudaFuncAttributeMaxDynamicSharedMemorySize, SMEMSZ);
    cudaFuncSetAttribute(tgemm<0,0,1,1>, cudaFuncAttributeMaxDynamicSharedMemorySize, SMEMSZ);
    cudaFuncSetAttribute(tgemm<0,0,SPLK,0>, cudaFuncAttributeMaxDynamicSharedMemorySize, SMEMSZ);
    cudaFuncSetAttribute(tgemm<3,1,1,0>, cudaFuncAttributeMaxDynamicSharedMemorySize, SMEMSZ);
    cudaFuncSetAttribute(tgemm<4,0,1,0>, cudaFuncAttributeMaxDynamicSharedMemorySize, SMEMSZ);
    cudaFuncSetAttribute(attn_gemm<0>, cudaFuncAttributeMaxDynamicSharedMemorySize, SMEMSZ);
    cudaFuncSetAttribute(attn_gemm<1>, cudaFuncAttributeMaxDynamicSharedMemorySize, SMEMSZ);

    dim3 tb32(32, 8);

    // weight transposes (one-time)
    transpose_w<<<dim3(D_/32,   D_/32),   tb32>>>(Wq, p_WqT, D_,   D_);
    transpose_w<<<dim3(D_/32,   C_/32),   tb32>>>(Wk, p_WkT, C_,   D_);
    transpose_w<<<dim3(D_/32,   C_/32),   tb32>>>(Wv, p_WvT, C_,   D_);
    transpose_w<<<dim3(MLP_/32, D_/32),   tb32>>>(W1, p_W1T, D_,   MLP_);
    transpose_w<<<dim3(D_/32,   MLP_/32), tb32>>>(W2, p_W2T, MLP_, D_);

    // input LN + transpose
    input_stats<<<(B_ * L_) / 256, 256>>>(x);
    transpose_norm<<<dim3(HW_ / 32, C_ / 32, B_), tb32>>>(x, lin_g, lin_b);

    // k projection (half out); v projection writes v^T directly (OUTT)
    tgemm<0,1,1,0><<<dim3(D_/128, (B_*L_)/128, 1), 256, SMEMSZ>>>(
        p_xn, p_WkT, p_k, C_, C_, D_, 0, 0, 0, nullptr, nullptr, 1.f);
    tgemm<0,0,1,1><<<dim3(D_/128, (B_*L_)/128, 1), 256, SMEMSZ>>>(
        p_xn, p_WvT, p_vT, C_, C_, L_, 0, 0, 0, nullptr, nullptr, 1.f);

    bcast_tmpl<<<(B_ * N_ * D_) / 256, 256>>>(ti);

    for (int it = 0; it < TITER; it++) {
        // t = LN(templates); q = (t @ Wq) * scale  (half out)
        ln_rows<<<B_ * N_, 256>>>(p_tmpl, p_t2, lt_g, lt_b);
        tgemm<0,1,1,0><<<dim3(D_/128, (B_*N_)/128, 1), 256, SMEMSZ>>>(
            p_t2, p_WqT, p_q, D_, D_, D_, 0, 0, 0, nullptr, nullptr, SCALE_);

        // fused logits GEMM + softmax + attnT + colsum partials
        if (it == TITER - 1) attn_gemm<1><<<dim3(1, L_/128, B_), 256, SMEMSZ>>>();
        else                 attn_gemm<0><<<dim3(1, L_/128, B_), 256, SMEMSZ>>>();

        // update: split-K partials of attn^T @ v
        tgemm<0,0,SPLK,0><<<dim3(D_/128, N_/128, B_ * SPLK), 256, SMEMSZ>>>(
            p_attnT, p_vT, p_part, L_, L_ / SPLK, D_,
            (long long)N_ * L_, (long long)D_ * L_, (long long)N_ * D_,
            nullptr, nullptr, 1.f);

        // fused colsum-finalize + reduce + residual + LN(lm) -> t2
        update_ln<<<B_ * N_, 256>>>(lm_g, lm_b);

        // MLP on t2: templates += relu(t2@W1+b1)@W2 + b2
        tgemm<3,1,1,0><<<dim3(MLP_/128, (B_*N_)/128, 1), 256, SMEMSZ>>>(
            p_t2, p_W1T, p_h, D_, D_, MLP_, 0, 0, 0, nullptr, b1, 1.f);
        tgemm<4,0,1,0><<<dim3(D_/128, (B_*N_)/128, 1), 256, SMEMSZ>>>(
            p_h, p_W2T, p_tmpl, MLP_, MLP_, D_, 0, 0, 0, p_tmpl, b2, 1.f);
    }

    out_templates_k<<<dim3(N_ / 32, D_ / 32, B_), tb32>>>(out_t);
    out_attn_k<<<dim3(L_ / 32, N_ / 32, B_), tb32>>>(out_a);
}

// round 9
// speedup vs baseline: 6.3216x; 1.0505x over previous
#include <cuda_runtime.h>
#include <cuda_fp16.h>
#include <cstdint>

// ---------------- problem constants ----------------
#define B_    8
#define C_    1024       // INPUT_DIM
#define HW_   4096       // H*W
#define L_    4096       // sequence length = H*W
#define D_    1024       // DIM
#define N_    256        // N_SLOTS
#define MLP_  512        // MLP_DIM
#define TITER 6
#define EPS_  1e-5f
#define SCALE_ 0.03125f  // DIM^-0.5
#define SPLK  2          // split-K factor for update GEMM

// ---------------- scratch (device globals; no allocation allowed) ----------------
__device__ float g_tmpl[B_*N_*D_];                 // fp32 residual stream
__device__ float g_cspart[B_*32*N_];
__device__ float g_csinv[B_*N_];
__device__ float g_part[(size_t)SPLK*B_*N_*D_];    // split-K partials (16 MB)

__device__ __half g_xn_h [(size_t)B_*L_*C_];       // 64 MB
__device__ __half g_k_h  [(size_t)B_*L_*D_];       // 64 MB
__device__ __half g_vT_h [(size_t)B_*D_*L_];       // 64 MB
__device__ __half g_attnT_h[(size_t)B_*N_*L_];     // 16 MB
__device__ __half g_q_h  [B_*N_*D_];
__device__ __half g_t2_h [B_*N_*D_];
__device__ __half g_h_h  [B_*N_*MLP_];
__device__ __half g_WqT_h[D_*D_];
__device__ __half g_WkT_h[D_*C_];
__device__ __half g_WvT_h[D_*C_];
__device__ __half g_W1T_h[MLP_*D_];
__device__ __half g_W2T_h[D_*MLP_];

// ---------------- helpers ----------------
__device__ __forceinline__ uint32_t smem_u32(const void* p) {
    uint32_t a;
    asm("{ .reg .u64 t; cvta.to.shared.u64 t, %1; cvt.u32.u64 %0, t; }" : "=r"(a) : "l"(p));
    return a;
}
__device__ __forceinline__ void cp16(uint32_t s, const void* g) {
    asm volatile("cp.async.cg.shared.global [%0], [%1], 16;\n" :: "r"(s), "l"(g));
}
#define CP_COMMIT() asm volatile("cp.async.commit_group;\n" ::: "memory")
#define CP_WAIT(N)  asm volatile("cp.async.wait_group %0;\n" :: "n"(N) : "memory")

__device__ __forceinline__ void ldsm4(uint32_t (&r)[4], uint32_t addr) {
    asm volatile("ldmatrix.sync.aligned.m8n8.x4.shared.b16 {%0,%1,%2,%3}, [%4];"
                 : "=r"(r[0]), "=r"(r[1]), "=r"(r[2]), "=r"(r[3]) : "r"(addr));
}
__device__ __forceinline__ void mma16816(float (&c)[4], const uint32_t (&a)[4],
                                         uint32_t b0, uint32_t b1) {
    asm volatile(
        "mma.sync.aligned.m16n8k16.row.col.f32.f16.f16.f32 "
        "{%0,%1,%2,%3}, {%4,%5,%6,%7}, {%8,%9}, {%0,%1,%2,%3};"
        : "+f"(c[0]), "+f"(c[1]), "+f"(c[2]), "+f"(c[3])
        : "r"(a[0]), "r"(a[1]), "r"(a[2]), "r"(a[3]), "r"(b0), "r"(b1));
}

// ================= generic tensor-core GEMM (fp16 mma.sync m16n8k16) =================
#define KC_ 64
#define SROW 72
#define STAGEH (128 * SROW)   // halves per operand stage

template<int EPI, int OUTH, int SPLITK, int OUTT>
__global__ void __launch_bounds__(256, 2)
tgemm(const __half* __restrict__ A, const __half* __restrict__ Bm,
      void* __restrict__ Cv, int Kld, int Klen, int ldc,
      long long sA, long long sB, long long sC,
      const float* __restrict__ res, const float* __restrict__ bias, float alpha) {
    extern __shared__ __half sh[];
    const uint32_t su = smem_u32(sh);

    const int tid  = threadIdx.x;
    const int wid  = tid >> 5;
    const int lane = tid & 31;
    const int wm = (wid >> 1) * 32;
    const int wn = (wid & 1) * 64;

    const int z = blockIdx.z;
    const int bz = (SPLITK > 1) ? z / SPLITK : z;
    const int sk = (SPLITK > 1) ? z % SPLITK : 0;
    A  += (size_t)bz * sA + (size_t)sk * Klen;
    Bm += (size_t)bz * sB + (size_t)sk * Klen;
    float*  Cf;
    __half* Ch = (__half*)Cv;
    if (SPLITK > 1) Cf = (float*)Cv + (size_t)z * sC;
    else            Cf = (float*)Cv + (OUTH ? 0 : (size_t)bz * sC);
    if (OUTH && !OUTT) Ch = (__half*)Cv + (size_t)bz * sC;
    if (EPI == 4) res += (size_t)bz * sC;

    const int m0 = blockIdx.y * 128;
    const int n0 = blockIdx.x * 128;
    const __half* gA = A + (size_t)m0 * Kld;
    const __half* gB = Bm + (size_t)n0 * Kld;

    float acc[2][8][4];
    #pragma unroll
    for (int i = 0; i < 2; i++)
        #pragma unroll
        for (int j = 0; j < 8; j++)
            #pragma unroll
            for (int r = 0; r < 4; r++) acc[i][j][r] = 0.f;

    auto load_chunk = [&](int c) {
        int buf = c & 1;
        uint32_t as = su + (uint32_t)(buf * STAGEH) * 2u;
        uint32_t bs = su + (uint32_t)((2 + buf) * STAGEH) * 2u;
        const __half* ga = gA + c * KC_;
        const __half* gb = gB + c * KC_;
        #pragma unroll
        for (int i = 0; i < 4; i++) {
            int e = tid + i * 256;
            int row = e >> 3;
            int c8 = (e & 7) * 8;
            uint32_t so = (uint32_t)(row * SROW + c8) * 2u;
            cp16(as + so, ga + (size_t)row * Kld + c8);
            cp16(bs + so, gb + (size_t)row * Kld + c8);
        }
        CP_COMMIT();
    };

    const int NC = Klen / KC_;
    load_chunk(0);

    const int rsel = (lane & 7) + ((lane >> 3) & 1) * 8;
    const int ksel = ((lane >> 4) & 1) * 8;

    for (int c = 0; c < NC; c++) {
        if (c + 1 < NC) { load_chunk(c + 1); CP_WAIT(1); }
        else            { CP_WAIT(0); }
        __syncthreads();

        int buf = c & 1;
        uint32_t abase = su + (uint32_t)(buf * STAGEH) * 2u;
        uint32_t bbase = su + (uint32_t)((2 + buf) * STAGEH) * 2u;

        #pragma unroll
        for (int ks = 0; ks < 4; ks++) {
            const int k0 = ks * 16 + ksel;
            uint32_t a[2][4];
            #pragma unroll
            for (int mf = 0; mf < 2; mf++)
                ldsm4(a[mf], abase + (uint32_t)((wm + mf * 16 + rsel) * SROW + k0) * 2u);
            uint32_t b[4][4];
            #pragma unroll
            for (int np = 0; np < 4; np++)
                ldsm4(b[np], bbase + (uint32_t)((wn + np * 16 + rsel) * SROW + k0) * 2u);
            #pragma unroll
            for (int mf = 0; mf < 2; mf++)
                #pragma unroll
                for (int nf = 0; nf < 8; nf++)
                    mma16816(acc[mf][nf], a[mf], b[nf >> 1][nf & 1], b[nf >> 1][2 + (nf & 1)]);
        }
        __syncthreads();
    }

    if (OUTT) {
        __half* stg = sh;
        #pragma unroll
        for (int mf = 0; mf < 2; mf++)
            #pragma unroll
            for (int h = 0; h < 2; h++) {
                int ml = wm + mf * 16 + h * 8 + (lane >> 2);
                #pragma unroll
                for (int nf = 0; nf < 8; nf++) {
                    int nl = wn + nf * 8 + (lane & 3) * 2;
                    stg[nl * 136 + ml]       = __float2half_rn(acc[mf][nf][h * 2 + 0]);
                    stg[(nl + 1) * 136 + ml] = __float2half_rn(acc[mf][nf][h * 2 + 1]);
                }
            }
        __syncthreads();
        int b = m0 >> 12;
        int l0 = m0 & (L_ - 1);
        __half* dst = Ch + (size_t)b * D_ * L_ + (size_t)n0 * L_ + l0;
        int r = tid >> 1, c0 = (tid & 1) * 64;
        const uint4* s4 = (const uint4*)(stg + r * 136 + c0);
        uint4* d4 = (uint4*)(dst + (size_t)r * L_ + c0);
        #pragma unroll
        for (int i = 0; i < 8; i++) d4[i] = s4[i];
        return;
    }

    #pragma unroll
    for (int mf = 0; mf < 2; mf++) {
        #pragma unroll
        for (int h = 0; h < 2; h++) {
            int m = m0 + wm + mf * 16 + h * 8 + (lane >> 2);
            #pragma unroll
            for (int nf = 0; nf < 8; nf++) {
                int n = n0 + wn + nf * 8 + (lane & 3) * 2;
                size_t idx = (size_t)m * ldc + n;
                float v0 = acc[mf][nf][h * 2 + 0];
                float v1 = acc[mf][nf][h * 2 + 1];
                if (EPI == 0)      { v0 *= alpha; v1 *= alpha; }
                else if (EPI == 3) { v0 = fmaxf(v0 + bias[n], 0.f); v1 = fmaxf(v1 + bias[n + 1], 0.f); }
                else if (EPI == 4) { v0 = res[idx] + v0 + bias[n]; v1 = res[idx + 1] + v1 + bias[n + 1]; }
                if (OUTH) *(__half2*)&Ch[idx] = __floats2half2_rn(v0, v1);
                else      *(float2*)&Cf[idx] = make_float2(v0, v1);
            }
        }
    }
}

// ================= fused logits GEMM + softmax + attnT + colsum =================
// Tile M=128 x N=256 (full slot dim), KC=32, grid (1, L/128, B).
#define ATROW 40
#define ATSTAGE (384 * ATROW)    // halves per stage (A 128 rows + B 256 rows)

__global__ void __launch_bounds__(256, 1)
attn_gemm() {
    extern __shared__ __half sh[];
    char* sc = (char*)sh;
    const uint32_t su = smem_u32(sh);
    const int tid = threadIdx.x, wid = tid >> 5, lane = tid & 31;
    const int wm = (wid >> 1) * 32, wn = (wid & 1) * 128;
    const int b = blockIdx.z, m0 = blockIdx.y * 128;
    const __half* gA = g_k_h + ((size_t)b * L_ + m0) * D_;
    const __half* gB = g_q_h + (size_t)b * N_ * D_;

    float acc[2][16][4];
    #pragma unroll
    for (int i = 0; i < 2; i++)
        #pragma unroll
        for (int j = 0; j < 16; j++)
            #pragma unroll
            for (int r = 0; r < 4; r++) acc[i][j][r] = 0.f;

    auto load_chunk = [&](int c) {
        uint32_t st = su + (uint32_t)((c & 1) * ATSTAGE) * 2u;
        #pragma unroll
        for (int i = 0; i < 2; i++) {
            int e = tid + i * 256;
            int row = e >> 2, qq = (e & 3) * 8;
            cp16(st + (uint32_t)(row * ATROW + qq) * 2u, gA + (size_t)row * D_ + c * 32 + qq);
        }
        #pragma unroll
        for (int i = 0; i < 4; i++) {
            int e = tid + i * 256;
            int row = e >> 2, qq = (e & 3) * 8;
            cp16(st + (uint32_t)((128 + row) * ATROW + qq) * 2u, gB + (size_t)row * D_ + c * 32 + qq);
        }
        CP_COMMIT();
    };

    const int NC = D_ / 32;
    load_chunk(0);
    const int rsel = (lane & 7) + ((lane >> 3) & 1) * 8;
    const int ksel = ((lane >> 4) & 1) * 8;

    for (int c = 0; c < NC; c++) {
        if (c + 1 < NC) { load_chunk(c + 1); CP_WAIT(1); }
        else            { CP_WAIT(0); }
        __syncthreads();
        uint32_t abase = su + (uint32_t)((c & 1) * ATSTAGE) * 2u;
        uint32_t bbase = abase + (uint32_t)(128 * ATROW) * 2u;
        #pragma unroll
        for (int ks = 0; ks < 2; ks++) {
            const int k0 = ks * 16 + ksel;
            uint32_t a[2][4];
            #pragma unroll
            for (int mf = 0; mf < 2; mf++)
                ldsm4(a[mf], abase + (uint32_t)((wm + mf * 16 + rsel) * ATROW + k0) * 2u);
            uint32_t bf[8][4];
            #pragma unroll
            for (int np = 0; np < 8; np++)
                ldsm4(bf[np], bbase + (uint32_t)((wn + np * 16 + rsel) * ATROW + k0) * 2u);
            #pragma unroll
            for (int mf = 0; mf < 2; mf++)
                #pragma unroll
                for (int nf = 0; nf < 16; nf++)
                    mma16816(acc[mf][nf], a[mf], bf[nf >> 1][nf & 1], bf[nf >> 1][2 + (nf & 1)]);
        }
        __syncthreads();
    }

    // ---- softmax epilogue ----
    __half* stg = sh;                           // [256 cols][136] transposed halves
    float* redv = (float*)(sc + 69632);         // 256 floats
    const int nwh = (wid & 1);
    float mx4[4], inv4[4];

    #pragma unroll
    for (int r = 0; r < 4; r++) {               // row max (warp-local 128 cols)
        int mf = r >> 1, hh = r & 1;
        float m = -1e30f;
        #pragma unroll
        for (int nf = 0; nf < 16; nf++)
            m = fmaxf(m, fmaxf(acc[mf][nf][hh * 2], acc[mf][nf][hh * 2 + 1]));
        m = fmaxf(m, __shfl_xor_sync(0xffffffffu, m, 1));
        m = fmaxf(m, __shfl_xor_sync(0xffffffffu, m, 2));
        if ((lane & 3) == 0)
            redv[nwh * 128 + wm + mf * 16 + hh * 8 + (lane >> 2)] = m;
    }
    __syncthreads();
    #pragma unroll
    for (int r = 0; r < 4; r++) {
        int rowl = wm + (r >> 1) * 16 + (r & 1) * 8 + (lane >> 2);
        mx4[r] = fmaxf(redv[rowl], redv[128 + rowl]);
    }
    __syncthreads();
    #pragma unroll
    for (int r = 0; r < 4; r++) {               // exp + row sum
        int mf = r >> 1, hh = r & 1;
        float s = 0.f;
        #pragma unroll
        for (int nf = 0; nf < 16; nf++) {
            float e0 = __expf(acc[mf][nf][hh * 2]     - mx4[r]);
            float e1 = __expf(acc[mf][nf][hh * 2 + 1] - mx4[r]);
            acc[mf][nf][hh * 2] = e0; acc[mf][nf][hh * 2 + 1] = e1;
            s += e0 + e1;
        }
        s += __shfl_xor_sync(0xffffffffu, s, 1);
        s += __shfl_xor_sync(0xffffffffu, s, 2);
        if ((lane & 3) == 0)
            redv[nwh * 128 + wm + mf * 16 + hh * 8 + (lane >> 2)] = s;
    }
    __syncthreads();
    #pragma unroll
    for (int r = 0; r < 4; r++) {
        int rowl = wm + (r >> 1) * 16 + (r & 1) * 8 + (lane >> 2);
        inv4[r] = 1.f / (redv[rowl] + redv[128 + rowl]);
    }
    #pragma unroll
    for (int r = 0; r < 4; r++) {
        int mf = r >> 1, hh = r & 1;
        int rowl = wm + mf * 16 + hh * 8 + (lane >> 2);
        #pragma unroll
        for (int nf = 0; nf < 16; nf++) {
            float p0 = acc[mf][nf][hh * 2]     * inv4[r] + 1e-8f;
            float p1 = acc[mf][nf][hh * 2 + 1] * inv4[r] + 1e-8f;
            int col = wn + nf * 8 + (lane & 3) * 2;
            stg[col * 136 + rowl]       = __float2half_rn(p0);
            stg[(col + 1) * 136 + rowl] = __float2half_rn(p1);
        }
    }
    __syncthreads();
    // colsum + coalesced attnT write (thread t owns slot n = t)
    {
        float cs = 0.f;
        const uint4* s4 = (const uint4*)(stg + tid * 136);
        uint4* d4 = (uint4*)(g_attnT_h + ((size_t)b * N_ + tid) * L_ + m0);
        #pragma unroll
        for (int j = 0; j < 16; j++) {
            uint4 u = s4[j];
            d4[j] = u;
            const __half2* hp = (const __half2*)&u;
            #pragma unroll
            for (int t = 0; t < 4; t++) {
                float2 f = __half22float2(hp[t]);
                cs += f.x + f.y;
            }
        }
        g_cspart[((size_t)b * 32 + blockIdx.y) * N_ + tid] = cs;
    }
}

// ---------------- block reduction ----------------
__device__ __forceinline__ float block_sum(float v) {
    __shared__ float shm[8];
    __shared__ float tot;
    #pragma unroll
    for (int o = 16; o; o >>= 1) v += __shfl_xor_sync(0xffffffffu, v, o);
    if ((threadIdx.x & 31) == 0) shm[threadIdx.x >> 5] = v;
    __syncthreads();
    if (threadIdx.x == 0) {
        float s = 0.f;
        #pragma unroll
        for (int i = 0; i < 8; i++) s += shm[i];
        tot = s;
    }
    __syncthreads();
    return tot;
}

// ---- fused: colsum finalize + split-K reduce + residual + LayerNorm(lm) -> t2 half ----
__global__ void update_ln(const float* __restrict__ gam, const float* __restrict__ bet) {
    int row = blockIdx.x;                 // b*N + n
    int b = row >> 8, n = row & (N_ - 1);
    int t = threadIdx.x;
    float cp = (t < 32) ? g_cspart[((size_t)b * 32 + t) * N_ + n] : 0.f;
    float tot = block_sum(cp);
    float inv = 1.f / tot;
    if (t == 0) g_csinv[row] = inv;
    size_t eb = (size_t)row * 1024 + t * 4;
    float4 u = *(const float4*)&g_tmpl[eb];
    float4 ps = make_float4(0.f, 0.f, 0.f, 0.f);
    #pragma unroll
    for (int sk = 0; sk < SPLK; sk++) {
        float4 pp = *(const float4*)&g_part[((size_t)(b * SPLK + sk) * N_ + n) * 1024 + t * 4];
        ps.x += pp.x; ps.y += pp.y; ps.z += pp.z; ps.w += pp.w;
    }
    u.x += inv * ps.x; u.y += inv * ps.y; u.z += inv * ps.z; u.w += inv * ps.w;
    float s1 = block_sum(u.x + u.y + u.z + u.w);
    float mu = s1 * (1.f / 1024.f);
    float dx = u.x - mu, dy = u.y - mu, dz = u.z - mu, dw = u.w - mu;
    float ss = block_sum(dx*dx + dy*dy + dz*dz + dw*dw);
    float rs = rsqrtf(ss * (1.f / 1024.f) + EPS_);
    *(float4*)&g_tmpl[eb] = u;
    float4 g4 = ((const float4*)gam)[t];
    float4 b4 = ((const float4*)bet)[t];
    __half2* o = (__half2*)(g_t2_h + (size_t)row * 1024);
    o[t * 2 + 0] = __floats2half2_rn(dx * rs * g4.x + b4.x, dy * rs * g4.y + b4.y);
    o[t * 2 + 1] = __floats2half2_rn(dz * rs * g4.z + b4.z, dw * rs * g4.w + b4.w);
}

// ================= non-GEMM kernels =================
// fused input LN: stats (pass 1) + transpose+normalize (pass 2, L2-resident re-read)
__global__ void norm_input(const float* __restrict__ x,
                           const float* __restrict__ gamma,
                           const float* __restrict__ beta) {
    __shared__ float S[8][33], SS[8][33];
    __shared__ float MU[32], RS[32];
    __shared__ float tile[32][33];
    int b = blockIdx.y, l0 = blockIdx.x * 32;
    int tx = threadIdx.x, ty = threadIdx.y;
    const float* xb = x + (size_t)b * C_ * HW_ + l0;
    // pass 1: per-l stats
    float s = 0.f, ss = 0.f;
    for (int c = ty; c < C_; c += 8) {
        float v = xb[(size_t)c * HW_ + tx];
        s += v; ss += v * v;
    }
    S[ty][tx] = s; SS[ty][tx] = ss;
    __syncthreads();
    if (ty == 0) {
        float a = 0.f, b2 = 0.f;
        #pragma unroll
        for (int i = 0; i < 8; i++) { a += S[i][tx]; b2 += SS[i][tx]; }
        float mu = a * (1.f / C_);
        float var = b2 * (1.f / C_) - mu * mu;
        MU[tx] = mu;
        RS[tx] = rsqrtf(fmaxf(var, 0.f) + EPS_);
    }
    __syncthreads();
    // pass 2: 32x32 tiles, transpose + normalize + half write
    for (int c0 = 0; c0 < C_; c0 += 32) {
        #pragma unroll
        for (int r = 0; r < 4; r++)
            tile[ty + 8*r][tx] = xb[(size_t)(c0 + ty + 8*r) * HW_ + tx];
        __syncthreads();
        #pragma unroll
        for (int r = 0; r < 4; r++) {
            int lr = ty + 8*r;
            int c = c0 + tx;
            g_xn_h[((size_t)(b * L_ + l0 + lr)) * C_ + c] =
                __float2half_rn((tile[tx][lr] - MU[lr]) * RS[lr] * gamma[c] + beta[c]);
        }
        __syncthreads();
    }
}

__global__ void transpose_w(const float* __restrict__ in, __half* __restrict__ out,
                            int R, int Ccols) {
    __shared__ float tile[32][33];
    int r0 = blockIdx.y * 32, c0 = blockIdx.x * 32;
    int tx = threadIdx.x, ty = threadIdx.y;
    #pragma unroll
    for (int i = 0; i < 4; i++)
        tile[ty + 8*i][tx] = in[(size_t)(r0 + ty + 8*i) * Ccols + c0 + tx];
    __syncthreads();
    #pragma unroll
    for (int i = 0; i < 4; i++)
        out[(size_t)(c0 + ty + 8*i) * R + r0 + tx] = __float2half_rn(tile[tx][ty + 8*i]);
}

__global__ void bcast_tmpl(const float* __restrict__ ti) {
    int i = blockIdx.x * 256 + threadIdx.x;
    g_tmpl[i] = ti[i & (N_*D_ - 1)];
}

__global__ void ln_rows(const float* __restrict__ in, __half* __restrict__ out,
                        const float* __restrict__ gamma, const float* __restrict__ beta) {
    int row = blockIdx.x;
    int t = threadIdx.x;
    float4 v = ((const float4*)(in + (size_t)row * 1024))[t];
    float s = block_sum(v.x + v.y + v.z + v.w);
    float mu = s * (1.f / 1024.f);
    float dx = v.x - mu, dy = v.y - mu, dz = v.z - mu, dw = v.w - mu;
    float ss = block_sum(dx*dx + dy*dy + dz*dz + dw*dw);
    float rs = rsqrtf(ss * (1.f / 1024.f) + EPS_);
    float4 g4 = ((const float4*)gamma)[t];
    float4 b4 = ((const float4*)beta)[t];
    __half2* orow = (__half2*)(out + (size_t)row * 1024);
    orow[t * 2 + 0] = __floats2half2_rn(dx * rs * g4.x + b4.x, dy * rs * g4.y + b4.y);
    orow[t * 2 + 1] = __floats2half2_rn(dz * rs * g4.z + b4.z, dw * rs * g4.w + b4.w);
}

__global__ void out_templates_k(float* __restrict__ out) {
    __shared__ float tile[32][33];
    int b = blockIdx.z;
    int n0 = blockIdx.x * 32, d0 = blockIdx.y * 32;
    int tx = threadIdx.x, ty = threadIdx.y;
    const float* tp = g_tmpl + (size_t)b * N_ * D_;
    #pragma unroll
    for (int r = 0; r < 4; r++)
        tile[ty + 8*r][tx] = tp[(size_t)(n0 + ty + 8*r) * D_ + d0 + tx];
    __syncthreads();
    float* op = out + (size_t)b * D_ * N_;
    #pragma unroll
    for (int r = 0; r < 4; r++)
        op[(size_t)(d0 + ty + 8*r) * N_ + n0 + tx] = tile[tx][ty + 8*r];
}

// out_attn[b][n][l] = half attnT[b][n][l] * csinv[b][n]   (fully coalesced)
__global__ void out_attn_k(float* __restrict__ out) {
    size_t i = (size_t)blockIdx.x * 256 + threadIdx.x;   // over B*N*L
    out[i] = __half2float(g_attnT_h[i]) * g_csinv[i >> 12];
}

// ================= launch =================
extern "C" void kernel_launch(void* const* d_in, const int* in_sizes, int n_in,
                              void* d_out, int out_size) {
    const float* x      = (const float*)d_in[0];
    const float* ti     = (const float*)d_in[1];
    const float* Wq     = (const float*)d_in[2];
    const float* Wk     = (const float*)d_in[3];
    const float* Wv     = (const float*)d_in[4];
    const float* lin_g  = (const float*)d_in[5];
    const float* lin_b  = (const float*)d_in[6];
    const float* lt_g   = (const float*)d_in[7];
    const float* lt_b   = (const float*)d_in[8];
    const float* lm_g   = (const float*)d_in[9];
    const float* lm_b   = (const float*)d_in[10];
    const float* W1     = (const float*)d_in[11];
    const float* b1     = (const float*)d_in[12];
    const float* W2     = (const float*)d_in[13];
    const float* b2     = (const float*)d_in[14];
    float* out_t = (float*)d_out;                          // [B, D, N]
    float* out_a = (float*)d_out + (size_t)B_ * D_ * N_;   // [B, N, H, W]

    float *p_tmpl, *p_part;
    __half *p_xn, *p_k, *p_vT, *p_attnT, *p_q, *p_t2, *p_h;
    __half *p_WqT, *p_WkT, *p_WvT, *p_W1T, *p_W2T;
    cudaGetSymbolAddress((void**)&p_tmpl, g_tmpl);
    cudaGetSymbolAddress((void**)&p_part, g_part);
    cudaGetSymbolAddress((void**)&p_xn, g_xn_h);
    cudaGetSymbolAddress((void**)&p_k, g_k_h);
    cudaGetSymbolAddress((void**)&p_vT, g_vT_h);
    cudaGetSymbolAddress((void**)&p_attnT, g_attnT_h);
    cudaGetSymbolAddress((void**)&p_q, g_q_h);
    cudaGetSymbolAddress((void**)&p_t2, g_t2_h);
    cudaGetSymbolAddress((void**)&p_h, g_h_h);
    cudaGetSymbolAddress((void**)&p_WqT, g_WqT_h);
    cudaGetSymbolAddress((void**)&p_WkT, g_WkT_h);
    cudaGetSymbolAddress((void**)&p_WvT, g_WvT_h);
    cudaGetSymbolAddress((void**)&p_W1T, g_W1T_h);
    cudaGetSymbolAddress((void**)&p_W2T, g_W2T_h);

    const int SMEMSZ = 4 * STAGEH * 2;   // 73728 bytes (covers attn_gemm: 70656)
    cudaFuncSetAttribute(tgemm<0,1,1,0>, cudaFuncAttributeMaxDynamicSharedMemorySize, SMEMSZ);
    cudaFuncSetAttribute(tgemm<0,0,1,1>, cudaFuncAttributeMaxDynamicSharedMemorySize, SMEMSZ);
    cudaFuncSetAttribute(tgemm<0,0,SPLK,0>, cudaFuncAttributeMaxDynamicSharedMemorySize, SMEMSZ);
    cudaFuncSetAttribute(tgemm<3,1,1,0>, cudaFuncAttributeMaxDynamicSharedMemorySize, SMEMSZ);
    cudaFuncSetAttribute(tgemm<4,0,1,0>, cudaFuncAttributeMaxDynamicSharedMemorySize, SMEMSZ);
    cudaFuncSetAttribute(attn_gemm, cudaFuncAttributeMaxDynamicSharedMemorySize, SMEMSZ);

    dim3 tb32(32, 8);

    // weight transposes (one-time)
    transpose_w<<<dim3(D_/32,   D_/32),   tb32>>>(Wq, p_WqT, D_,   D_);
    transpose_w<<<dim3(D_/32,   C_/32),   tb32>>>(Wk, p_WkT, C_,   D_);
    transpose_w<<<dim3(D_/32,   C_/32),   tb32>>>(Wv, p_WvT, C_,   D_);
    transpose_w<<<dim3(MLP_/32, D_/32),   tb32>>>(W1, p_W1T, D_,   MLP_);
    transpose_w<<<dim3(D_/32,   MLP_/32), tb32>>>(W2, p_W2T, MLP_, D_);

    // fused input LN (stats + transpose + normalize)
    norm_input<<<dim3(L_/32, B_), tb32>>>(x, lin_g, lin_b);

    // k projection (half out); v projection writes v^T directly (OUTT)
    tgemm<0,1,1,0><<<dim3(D_/128, (B_*L_)/128, 1), 256, SMEMSZ>>>(
        p_xn, p_WkT, p_k, C_, C_, D_, 0, 0, 0, nullptr, nullptr, 1.f);
    tgemm<0,0,1,1><<<dim3(D_/128, (B_*L_)/128, 1), 256, SMEMSZ>>>(
        p_xn, p_WvT, p_vT, C_, C_, L_, 0, 0, 0, nullptr, nullptr, 1.f);

    bcast_tmpl<<<(B_ * N_ * D_) / 256, 256>>>(ti);

    for (int it = 0; it < TITER; it++) {
        // t = LN(templates); q = (t @ Wq) * scale  (half out)
        ln_rows<<<B_ * N_, 256>>>(p_tmpl, p_t2, lt_g, lt_b);
        tgemm<0,1,1,0><<<dim3(D_/128, (B_*N_)/128, 1), 256, SMEMSZ>>>(
            p_t2, p_WqT, p_q, D_, D_, D_, 0, 0, 0, nullptr, nullptr, SCALE_);

        // fused logits GEMM + softmax + attnT + colsum partials
        attn_gemm<<<dim3(1, L_/128, B_), 256, SMEMSZ>>>();

        // update: split-K partials of attn^T @ v
        tgemm<0,0,SPLK,0><<<dim3(D_/128, N_/128, B_ * SPLK), 256, SMEMSZ>>>(
            p_attnT, p_vT, p_part, L_, L_ / SPLK, D_,
            (long long)N_ * L_, (long long)D_ * L_, (long long)N_ * D_,
            nullptr, nullptr, 1.f);

        // fused colsum-finalize + reduce + residual + LN(lm) -> t2
        update_ln<<<B_ * N_, 256>>>(lm_g, lm_b);

        // MLP on t2: templates += relu(t2@W1+b1)@W2 + b2
        tgemm<3,1,1,0><<<dim3(MLP_/128, (B_*N_)/128, 1), 256, SMEMSZ>>>(
            p_t2, p_W1T, p_h, D_, D_, MLP_, 0, 0, 0, nullptr, b1, 1.f);
        tgemm<4,0,1,0><<<dim3(D_/128, (B_*N_)/128, 1), 256, SMEMSZ>>>(
            p_h, p_W2T, p_tmpl, MLP_, MLP_, D_, 0, 0, 0, p_tmpl, b2, 1.f);
    }

    out_templates_k<<<dim3(N_ / 32, D_ / 32, B_), tb32>>>(out_t);
    out_attn_k<<<(B_ * N_ * L_) / 256, 256>>>(out_a);
}

// round 10
// speedup vs baseline: 6.8223x; 1.0792x over previous
#include <cuda_runtime.h>
#include <cuda_fp16.h>
#include <cstdint>

// ---------------- problem constants ----------------
#define B_    8
#define C_    1024       // INPUT_DIM
#define HW_   4096       // H*W
#define L_    4096       // sequence length = H*W
#define D_    1024       // DIM
#define N_    256        // N_SLOTS
#define MLP_  512        // MLP_DIM
#define TITER 6
#define EPS_  1e-5f
#define SCALE_ 0.03125f  // DIM^-0.5
#define SPLK  2          // split-K factor for update GEMM

// ---------------- scratch (device globals; no allocation allowed) ----------------
__device__ float g_tmpl[B_*N_*D_];                 // fp32 residual stream
__device__ float g_cspart[B_*32*N_];
__device__ float g_csinv[B_*N_];
__device__ float g_part[(size_t)SPLK*B_*N_*D_];    // split-K partials (16 MB)

__device__ __half g_xn_h [(size_t)B_*L_*C_];       // 64 MB
__device__ __half g_k_h  [(size_t)B_*L_*D_];       // 64 MB
__device__ __half g_vT_h [(size_t)B_*D_*L_];       // 64 MB
__device__ __half g_attnT_h[(size_t)B_*N_*L_];     // 16 MB
__device__ __half g_q_h  [B_*N_*D_];
__device__ __half g_t2_h [B_*N_*D_];
__device__ __half g_h_h  [B_*N_*MLP_];
__device__ __half g_WqT_h[D_*D_];
__device__ __half g_WkT_h[D_*C_];
__device__ __half g_WvT_h[D_*C_];
__device__ __half g_W1T_h[MLP_*D_];
__device__ __half g_W2T_h[D_*MLP_];

// ---------------- helpers ----------------
__device__ __forceinline__ uint32_t smem_u32(const void* p) {
    uint32_t a;
    asm("{ .reg .u64 t; cvta.to.shared.u64 t, %1; cvt.u32.u64 %0, t; }" : "=r"(a) : "l"(p));
    return a;
}
__device__ __forceinline__ void cp16(uint32_t s, const void* g) {
    asm volatile("cp.async.cg.shared.global [%0], [%1], 16;\n" :: "r"(s), "l"(g));
}
#define CP_COMMIT() asm volatile("cp.async.commit_group;\n" ::: "memory")
#define CP_WAIT(N)  asm volatile("cp.async.wait_group %0;\n" :: "n"(N) : "memory")

__device__ __forceinline__ void ldsm4(uint32_t (&r)[4], uint32_t addr) {
    asm volatile("ldmatrix.sync.aligned.m8n8.x4.shared.b16 {%0,%1,%2,%3}, [%4];"
                 : "=r"(r[0]), "=r"(r[1]), "=r"(r[2]), "=r"(r[3]) : "r"(addr));
}
__device__ __forceinline__ void mma16816(float (&c)[4], const uint32_t (&a)[4],
                                         uint32_t b0, uint32_t b1) {
    asm volatile(
        "mma.sync.aligned.m16n8k16.row.col.f32.f16.f16.f32 "
        "{%0,%1,%2,%3}, {%4,%5,%6,%7}, {%8,%9}, {%0,%1,%2,%3};"
        : "+f"(c[0]), "+f"(c[1]), "+f"(c[2]), "+f"(c[3])
        : "r"(a[0]), "r"(a[1]), "r"(a[2]), "r"(a[3]), "r"(b0), "r"(b1));
}

// ================= generic tensor-core GEMM (fp16 mma.sync m16n8k16) =================
// 3-stage cp.async pipeline, 1 __syncthreads per K-chunk, XOR-swizzled smem (64-half rows).
#define KC_ 64
#define TG_STAGE 32768           // bytes per stage (A 16KB + B 16KB)
#define TG_SMEM  (3 * TG_STAGE)  // 98304

template<int EPI, int OUTH, int SPLITK, int OUTT>
__global__ void __launch_bounds__(256, 2)
tgemm(const __half* __restrict__ A, const __half* __restrict__ Bm,
      void* __restrict__ Cv, int Kld, int Klen, int ldc,
      long long sA, long long sB, long long sC,
      const float* __restrict__ res, const float* __restrict__ bias, float alpha) {
    extern __shared__ __half sh[];
    const uint32_t su = smem_u32(sh);

    const int tid  = threadIdx.x;
    const int wid  = tid >> 5;
    const int lane = tid & 31;
    const int wm = (wid >> 1) * 32;
    const int wn = (wid & 1) * 64;

    const int z = blockIdx.z;
    const int bz = (SPLITK > 1) ? z / SPLITK : z;
    const int sk = (SPLITK > 1) ? z % SPLITK : 0;
    A  += (size_t)bz * sA + (size_t)sk * Klen;
    Bm += (size_t)bz * sB + (size_t)sk * Klen;
    float*  Cf;
    __half* Ch = (__half*)Cv;
    if (SPLITK > 1) Cf = (float*)Cv + (size_t)z * sC;
    else            Cf = (float*)Cv + (OUTH ? 0 : (size_t)bz * sC);
    if (OUTH && !OUTT) Ch = (__half*)Cv + (size_t)bz * sC;
    if (EPI == 4) res += (size_t)bz * sC;

    const int m0 = blockIdx.y * 128;
    const int n0 = blockIdx.x * 128;
    const __half* gA = A + (size_t)m0 * Kld;
    const __half* gB = Bm + (size_t)n0 * Kld;

    float acc[2][8][4];
    #pragma unroll
    for (int i = 0; i < 2; i++)
        #pragma unroll
        for (int j = 0; j < 8; j++)
            #pragma unroll
            for (int r = 0; r < 4; r++) acc[i][j][r] = 0.f;

    // swizzled store offset for (row, chunk[16B]): row*128 + ((ch ^ (row&7))<<4)
    auto load_chunk = [&](int c) {
        uint32_t st = su + (uint32_t)((c % 3) * TG_STAGE);
        const __half* ga = gA + c * KC_;
        const __half* gb = gB + c * KC_;
        #pragma unroll
        for (int i = 0; i < 4; i++) {
            int e = tid + i * 256;
            int row = e >> 3;
            int ch = e & 7;
            uint32_t so = (uint32_t)(row * 128 + ((ch ^ (row & 7)) << 4));
            cp16(st + so, ga + (size_t)row * Kld + ch * 8);
            cp16(st + 16384u + so, gb + (size_t)row * Kld + ch * 8);
        }
        CP_COMMIT();
    };

    const int NC = Klen / KC_;   // >= 8 always
    load_chunk(0);
    load_chunk(1);

    const int rsel = (lane & 7) + ((lane >> 3) & 1) * 8;  // row within 16
    const int kbit = (lane >> 4) & 1;                     // 16B half of k16 group
    uint32_t arb[2], arx[2], brb[4], brx[4];
    #pragma unroll
    for (int mf = 0; mf < 2; mf++) {
        int r = wm + mf * 16 + rsel;
        arb[mf] = (uint32_t)(r * 128); arx[mf] = (uint32_t)(r & 7);
    }
    #pragma unroll
    for (int np = 0; np < 4; np++) {
        int r = wn + np * 16 + rsel;
        brb[np] = (uint32_t)(r * 128); brx[np] = (uint32_t)(r & 7);
    }

    for (int c = 0; c < NC; c++) {
        CP_WAIT(1);          // groups 0..c complete
        __syncthreads();     // all warps done with chunk c-1
        if (c + 2 < NC) load_chunk(c + 2); else CP_COMMIT();

        uint32_t abase = su + (uint32_t)((c % 3) * TG_STAGE);
        uint32_t bbase = abase + 16384u;

        #pragma unroll
        for (int ks = 0; ks < 4; ks++) {
            const uint32_t kc2 = (uint32_t)(ks * 2) + kbit;
            uint32_t a[2][4];
            #pragma unroll
            for (int mf = 0; mf < 2; mf++)
                ldsm4(a[mf], abase + arb[mf] + (((kc2 ^ arx[mf])) << 4));
            uint32_t b[4][4];
            #pragma unroll
            for (int np = 0; np < 4; np++)
                ldsm4(b[np], bbase + brb[np] + (((kc2 ^ brx[np])) << 4));
            #pragma unroll
            for (int mf = 0; mf < 2; mf++)
                #pragma unroll
                for (int nf = 0; nf < 8; nf++)
                    mma16816(acc[mf][nf], a[mf], b[nf >> 1][nf & 1], b[nf >> 1][2 + (nf & 1)]);
        }
    }

    if (OUTT) {
        __syncthreads();     // all computes done before reusing stage smem
        __half* stg = sh;
        #pragma unroll
        for (int mf = 0; mf < 2; mf++)
            #pragma unroll
            for (int h = 0; h < 2; h++) {
                int ml = wm + mf * 16 + h * 8 + (lane >> 2);
                #pragma unroll
                for (int nf = 0; nf < 8; nf++) {
                    int nl = wn + nf * 8 + (lane & 3) * 2;
                    stg[nl * 136 + ml]       = __float2half_rn(acc[mf][nf][h * 2 + 0]);
                    stg[(nl + 1) * 136 + ml] = __float2half_rn(acc[mf][nf][h * 2 + 1]);
                }
            }
        __syncthreads();
        int b = m0 >> 12;
        int l0 = m0 & (L_ - 1);
        __half* dst = Ch + (size_t)b * D_ * L_ + (size_t)n0 * L_ + l0;
        int r = tid >> 1, c0 = (tid & 1) * 64;
        const uint4* s4 = (const uint4*)(stg + r * 136 + c0);
        uint4* d4 = (uint4*)(dst + (size_t)r * L_ + c0);
        #pragma unroll
        for (int i = 0; i < 8; i++) d4[i] = s4[i];
        return;
    }

    #pragma unroll
    for (int mf = 0; mf < 2; mf++) {
        #pragma unroll
        for (int h = 0; h < 2; h++) {
            int m = m0 + wm + mf * 16 + h * 8 + (lane >> 2);
            #pragma unroll
            for (int nf = 0; nf < 8; nf++) {
                int n = n0 + wn + nf * 8 + (lane & 3) * 2;
                size_t idx = (size_t)m * ldc + n;
                float v0 = acc[mf][nf][h * 2 + 0];
                float v1 = acc[mf][nf][h * 2 + 1];
                if (EPI == 0)      { v0 *= alpha; v1 *= alpha; }
                else if (EPI == 3) { v0 = fmaxf(v0 + bias[n], 0.f); v1 = fmaxf(v1 + bias[n + 1], 0.f); }
                else if (EPI == 4) { v0 = res[idx] + v0 + bias[n]; v1 = res[idx + 1] + v1 + bias[n + 1]; }
                if (OUTH) *(__half2*)&Ch[idx] = __floats2half2_rn(v0, v1);
                else      *(float2*)&Cf[idx] = make_float2(v0, v1);
            }
        }
    }
}

// ================= fused logits GEMM + softmax + attnT + colsum =================
// Tile M=128 x N=256, KC=32, 3-stage pipeline, 1 sync/chunk. grid (1, L/128, B).
#define ATROW 40
#define ATSTAGE (384 * ATROW)      // halves per stage
#define AT_SMEM (3 * ATSTAGE * 2)  // 92160 bytes

__global__ void __launch_bounds__(256, 1)
attn_gemm() {
    extern __shared__ __half sh[];
    char* sc = (char*)sh;
    const uint32_t su = smem_u32(sh);
    const int tid = threadIdx.x, wid = tid >> 5, lane = tid & 31;
    const int wm = (wid >> 1) * 32, wn = (wid & 1) * 128;
    const int b = blockIdx.z, m0 = blockIdx.y * 128;
    const __half* gA = g_k_h + ((size_t)b * L_ + m0) * D_;
    const __half* gB = g_q_h + (size_t)b * N_ * D_;

    float acc[2][16][4];
    #pragma unroll
    for (int i = 0; i < 2; i++)
        #pragma unroll
        for (int j = 0; j < 16; j++)
            #pragma unroll
            for (int r = 0; r < 4; r++) acc[i][j][r] = 0.f;

    auto load_chunk = [&](int c) {
        uint32_t st = su + (uint32_t)((c % 3) * ATSTAGE) * 2u;
        #pragma unroll
        for (int i = 0; i < 2; i++) {
            int e = tid + i * 256;
            int row = e >> 2, qq = (e & 3) * 8;
            cp16(st + (uint32_t)(row * ATROW + qq) * 2u, gA + (size_t)row * D_ + c * 32 + qq);
        }
        #pragma unroll
        for (int i = 0; i < 4; i++) {
            int e = tid + i * 256;
            int row = e >> 2, qq = (e & 3) * 8;
            cp16(st + (uint32_t)((128 + row) * ATROW + qq) * 2u, gB + (size_t)row * D_ + c * 32 + qq);
        }
        CP_COMMIT();
    };

    const int NC = D_ / 32;
    load_chunk(0);
    load_chunk(1);
    const int rsel = (lane & 7) + ((lane >> 3) & 1) * 8;
    const int ksel = ((lane >> 4) & 1) * 8;

    for (int c = 0; c < NC; c++) {
        CP_WAIT(1);
        __syncthreads();
        if (c + 2 < NC) load_chunk(c + 2); else CP_COMMIT();

        uint32_t abase = su + (uint32_t)((c % 3) * ATSTAGE) * 2u;
        uint32_t bbase = abase + (uint32_t)(128 * ATROW) * 2u;
        #pragma unroll
        for (int ks = 0; ks < 2; ks++) {
            const int k0 = ks * 16 + ksel;
            uint32_t a[2][4];
            #pragma unroll
            for (int mf = 0; mf < 2; mf++)
                ldsm4(a[mf], abase + (uint32_t)((wm + mf * 16 + rsel) * ATROW + k0) * 2u);
            uint32_t bf[8][4];
            #pragma unroll
            for (int np = 0; np < 8; np++)
                ldsm4(bf[np], bbase + (uint32_t)((wn + np * 16 + rsel) * ATROW + k0) * 2u);
            #pragma unroll
            for (int mf = 0; mf < 2; mf++)
                #pragma unroll
                for (int nf = 0; nf < 16; nf++)
                    mma16816(acc[mf][nf], a[mf], bf[nf >> 1][nf & 1], bf[nf >> 1][2 + (nf & 1)]);
        }
    }
    __syncthreads();    // computes done before stage smem is reused by epilogue

    // ---- softmax epilogue ----
    __half* stg = sh;                           // [256 cols][136] transposed halves
    float* redv = (float*)(sc + 69632);         // 256 floats
    const int nwh = (wid & 1);
    float mx4[4], inv4[4];

    #pragma unroll
    for (int r = 0; r < 4; r++) {               // row max (warp-local 128 cols)
        int mf = r >> 1, hh = r & 1;
        float m = -1e30f;
        #pragma unroll
        for (int nf = 0; nf < 16; nf++)
            m = fmaxf(m, fmaxf(acc[mf][nf][hh * 2], acc[mf][nf][hh * 2 + 1]));
        m = fmaxf(m, __shfl_xor_sync(0xffffffffu, m, 1));
        m = fmaxf(m, __shfl_xor_sync(0xffffffffu, m, 2));
        if ((lane & 3) == 0)
            redv[nwh * 128 + wm + mf * 16 + hh * 8 + (lane >> 2)] = m;
    }
    __syncthreads();
    #pragma unroll
    for (int r = 0; r < 4; r++) {
        int rowl = wm + (r >> 1) * 16 + (r & 1) * 8 + (lane >> 2);
        mx4[r] = fmaxf(redv[rowl], redv[128 + rowl]);
    }
    __syncthreads();
    #pragma unroll
    for (int r = 0; r < 4; r++) {               // exp + row sum
        int mf = r >> 1, hh = r & 1;
        float s = 0.f;
        #pragma unroll
        for (int nf = 0; nf < 16; nf++) {
            float e0 = __expf(acc[mf][nf][hh * 2]     - mx4[r]);
            float e1 = __expf(acc[mf][nf][hh * 2 + 1] - mx4[r]);
            acc[mf][nf][hh * 2] = e0; acc[mf][nf][hh * 2 + 1] = e1;
            s += e0 + e1;
        }
        s += __shfl_xor_sync(0xffffffffu, s, 1);
        s += __shfl_xor_sync(0xffffffffu, s, 2);
        if ((lane & 3) == 0)
            redv[nwh * 128 + wm + mf * 16 + hh * 8 + (lane >> 2)] = s;
    }
    __syncthreads();
    #pragma unroll
    for (int r = 0; r < 4; r++) {
        int rowl = wm + (r >> 1) * 16 + (r & 1) * 8 + (lane >> 2);
        inv4[r] = 1.f / (redv[rowl] + redv[128 + rowl]);
    }
    #pragma unroll
    for (int r = 0; r < 4; r++) {
        int mf = r >> 1, hh = r & 1;
        int rowl = wm + mf * 16 + hh * 8 + (lane >> 2);
        #pragma unroll
        for (int nf = 0; nf < 16; nf++) {
            float p0 = acc[mf][nf][hh * 2]     * inv4[r] + 1e-8f;
            float p1 = acc[mf][nf][hh * 2 + 1] * inv4[r] + 1e-8f;
            int col = wn + nf * 8 + (lane & 3) * 2;
            stg[col * 136 + rowl]       = __float2half_rn(p0);
            stg[(col + 1) * 136 + rowl] = __float2half_rn(p1);
        }
    }
    __syncthreads();
    // colsum + coalesced attnT write (thread t owns slot n = t)
    {
        float cs = 0.f;
        const uint4* s4 = (const uint4*)(stg + tid * 136);
        uint4* d4 = (uint4*)(g_attnT_h + ((size_t)b * N_ + tid) * L_ + m0);
        #pragma unroll
        for (int j = 0; j < 16; j++) {
            uint4 u = s4[j];
            d4[j] = u;
            const __half2* hp = (const __half2*)&u;
            #pragma unroll
            for (int t = 0; t < 4; t++) {
                float2 f = __half22float2(hp[t]);
                cs += f.x + f.y;
            }
        }
        g_cspart[((size_t)b * 32 + blockIdx.y) * N_ + tid] = cs;
    }
}

// ---------------- block reduction ----------------
__device__ __forceinline__ float block_sum(float v) {
    __shared__ float shm[8];
    __shared__ float tot;
    #pragma unroll
    for (int o = 16; o; o >>= 1) v += __shfl_xor_sync(0xffffffffu, v, o);
    if ((threadIdx.x & 31) == 0) shm[threadIdx.x >> 5] = v;
    __syncthreads();
    if (threadIdx.x == 0) {
        float s = 0.f;
        #pragma unroll
        for (int i = 0; i < 8; i++) s += shm[i];
        tot = s;
    }
    __syncthreads();
    return tot;
}

// ---- fused: colsum finalize + split-K reduce + residual + LayerNorm(lm) -> t2 half ----
__global__ void update_ln(const float* __restrict__ gam, const float* __restrict__ bet) {
    int row = blockIdx.x;                 // b*N + n
    int b = row >> 8, n = row & (N_ - 1);
    int t = threadIdx.x;
    float cp = (t < 32) ? g_cspart[((size_t)b * 32 + t) * N_ + n] : 0.f;
    float tot = block_sum(cp);
    float inv = 1.f / tot;
    if (t == 0) g_csinv[row] = inv;
    size_t eb = (size_t)row * 1024 + t * 4;
    float4 u = *(const float4*)&g_tmpl[eb];
    float4 ps = make_float4(0.f, 0.f, 0.f, 0.f);
    #pragma unroll
    for (int sk = 0; sk < SPLK; sk++) {
        float4 pp = *(const float4*)&g_part[((size_t)(b * SPLK + sk) * N_ + n) * 1024 + t * 4];
        ps.x += pp.x; ps.y += pp.y; ps.z += pp.z; ps.w += pp.w;
    }
    u.x += inv * ps.x; u.y += inv * ps.y; u.z += inv * ps.z; u.w += inv * ps.w;
    float s1 = block_sum(u.x + u.y + u.z + u.w);
    float mu = s1 * (1.f / 1024.f);
    float dx = u.x - mu, dy = u.y - mu, dz = u.z - mu, dw = u.w - mu;
    float ss = block_sum(dx*dx + dy*dy + dz*dz + dw*dw);
    float rs = rsqrtf(ss * (1.f / 1024.f) + EPS_);
    *(float4*)&g_tmpl[eb] = u;
    float4 g4 = ((const float4*)gam)[t];
    float4 b4 = ((const float4*)bet)[t];
    __half2* o = (__half2*)(g_t2_h + (size_t)row * 1024);
    o[t * 2 + 0] = __floats2half2_rn(dx * rs * g4.x + b4.x, dy * rs * g4.y + b4.y);
    o[t * 2 + 1] = __floats2half2_rn(dz * rs * g4.z + b4.z, dw * rs * g4.w + b4.w);
}

// ================= non-GEMM kernels =================
// fused input LN: stats (pass 1) + transpose+normalize (pass 2, L2-resident re-read)
__global__ void norm_input(const float* __restrict__ x,
                           const float* __restrict__ gamma,
                           const float* __restrict__ beta) {
    __shared__ float S[8][33], SS[8][33];
    __shared__ float MU[32], RS[32];
    __shared__ float tile[32][33];
    int b = blockIdx.y, l0 = blockIdx.x * 32;
    int tx = threadIdx.x, ty = threadIdx.y;
    const float* xb = x + (size_t)b * C_ * HW_ + l0;
    float s = 0.f, ss = 0.f;
    for (int c = ty; c < C_; c += 8) {
        float v = xb[(size_t)c * HW_ + tx];
        s += v; ss += v * v;
    }
    S[ty][tx] = s; SS[ty][tx] = ss;
    __syncthreads();
    if (ty == 0) {
        float a = 0.f, b2 = 0.f;
        #pragma unroll
        for (int i = 0; i < 8; i++) { a += S[i][tx]; b2 += SS[i][tx]; }
        float mu = a * (1.f / C_);
        float var = b2 * (1.f / C_) - mu * mu;
        MU[tx] = mu;
        RS[tx] = rsqrtf(fmaxf(var, 0.f) + EPS_);
    }
    __syncthreads();
    for (int c0 = 0; c0 < C_; c0 += 32) {
        #pragma unroll
        for (int r = 0; r < 4; r++)
            tile[ty + 8*r][tx] = xb[(size_t)(c0 + ty + 8*r) * HW_ + tx];
        __syncthreads();
        #pragma unroll
        for (int r = 0; r < 4; r++) {
            int lr = ty + 8*r;
            int c = c0 + tx;
            g_xn_h[((size_t)(b * L_ + l0 + lr)) * C_ + c] =
                __float2half_rn((tile[tx][lr] - MU[lr]) * RS[lr] * gamma[c] + beta[c]);
        }
        __syncthreads();
    }
}

__global__ void transpose_w(const float* __restrict__ in, __half* __restrict__ out,
                            int R, int Ccols) {
    __shared__ float tile[32][33];
    int r0 = blockIdx.y * 32, c0 = blockIdx.x * 32;
    int tx = threadIdx.x, ty = threadIdx.y;
    #pragma unroll
    for (int i = 0; i < 4; i++)
        tile[ty + 8*i][tx] = in[(size_t)(r0 + ty + 8*i) * Ccols + c0 + tx];
    __syncthreads();
    #pragma unroll
    for (int i = 0; i < 4; i++)
        out[(size_t)(c0 + ty + 8*i) * R + r0 + tx] = __float2half_rn(tile[tx][ty + 8*i]);
}

__global__ void bcast_tmpl(const float* __restrict__ ti) {
    int i = blockIdx.x * 256 + threadIdx.x;
    g_tmpl[i] = ti[i & (N_*D_ - 1)];
}

__global__ void ln_rows(const float* __restrict__ in, __half* __restrict__ out,
                        const float* __restrict__ gamma, const float* __restrict__ beta) {
    int row = blockIdx.x;
    int t = threadIdx.x;
    float4 v = ((const float4*)(in + (size_t)row * 1024))[t];
    float s = block_sum(v.x + v.y + v.z + v.w);
    float mu = s * (1.f / 1024.f);
    float dx = v.x - mu, dy = v.y - mu, dz = v.z - mu, dw = v.w - mu;
    float ss = block_sum(dx*dx + dy*dy + dz*dz + dw*dw);
    float rs = rsqrtf(ss * (1.f / 1024.f) + EPS_);
    float4 g4 = ((const float4*)gamma)[t];
    float4 b4 = ((const float4*)beta)[t];
    __half2* orow = (__half2*)(out + (size_t)row * 1024);
    orow[t * 2 + 0] = __floats2half2_rn(dx * rs * g4.x + b4.x, dy * rs * g4.y + b4.y);
    orow[t * 2 + 1] = __floats2half2_rn(dz * rs * g4.z + b4.z, dw * rs * g4.w + b4.w);
}

__global__ void out_templates_k(float* __restrict__ out) {
    __shared__ float tile[32][33];
    int b = blockIdx.z;
    int n0 = blockIdx.x * 32, d0 = blockIdx.y * 32;
    int tx = threadIdx.x, ty = threadIdx.y;
    const float* tp = g_tmpl + (size_t)b * N_ * D_;
    #pragma unroll
    for (int r = 0; r < 4; r++)
        tile[ty + 8*r][tx] = tp[(size_t)(n0 + ty + 8*r) * D_ + d0 + tx];
    __syncthreads();
    float* op = out + (size_t)b * D_ * N_;
    #pragma unroll
    for (int r = 0; r < 4; r++)
        op[(size_t)(d0 + ty + 8*r) * N_ + n0 + tx] = tile[tx][ty + 8*r];
}

// out_attn[b][n][l] = half attnT[b][n][l] * csinv[b][n]   (fully coalesced)
__global__ void out_attn_k(float* __restrict__ out) {
    size_t i = (size_t)blockIdx.x * 256 + threadIdx.x;   // over B*N*L
    out[i] = __half2float(g_attnT_h[i]) * g_csinv[i >> 12];
}

// ================= launch =================
extern "C" void kernel_launch(void* const* d_in, const int* in_sizes, int n_in,
                              void* d_out, int out_size) {
    const float* x      = (const float*)d_in[0];
    const float* ti     = (const float*)d_in[1];
    const float* Wq     = (const float*)d_in[2];
    const float* Wk     = (const float*)d_in[3];
    const float* Wv     = (const float*)d_in[4];
    const float* lin_g  = (const float*)d_in[5];
    const float* lin_b  = (const float*)d_in[6];
    const float* lt_g   = (const float*)d_in[7];
    const float* lt_b   = (const float*)d_in[8];
    const float* lm_g   = (const float*)d_in[9];
    const float* lm_b   = (const float*)d_in[10];
    const float* W1     = (const float*)d_in[11];
    const float* b1     = (const float*)d_in[12];
    const float* W2     = (const float*)d_in[13];
    const float* b2     = (const float*)d_in[14];
    float* out_t = (float*)d_out;                          // [B, D, N]
    float* out_a = (float*)d_out + (size_t)B_ * D_ * N_;   // [B, N, H, W]

    float *p_tmpl, *p_part;
    __half *p_xn, *p_k, *p_vT, *p_attnT, *p_q, *p_t2, *p_h;
    __half *p_WqT, *p_WkT, *p_WvT, *p_W1T, *p_W2T;
    cudaGetSymbolAddress((void**)&p_tmpl, g_tmpl);
    cudaGetSymbolAddress((void**)&p_part, g_part);
    cudaGetSymbolAddress((void**)&p_xn, g_xn_h);
    cudaGetSymbolAddress((void**)&p_k, g_k_h);
    cudaGetSymbolAddress((void**)&p_vT, g_vT_h);
    cudaGetSymbolAddress((void**)&p_attnT, g_attnT_h);
    cudaGetSymbolAddress((void**)&p_q, g_q_h);
    cudaGetSymbolAddress((void**)&p_t2, g_t2_h);
    cudaGetSymbolAddress((void**)&p_h, g_h_h);
    cudaGetSymbolAddress((void**)&p_WqT, g_WqT_h);
    cudaGetSymbolAddress((void**)&p_WkT, g_WkT_h);
    cudaGetSymbolAddress((void**)&p_WvT, g_WvT_h);
    cudaGetSymbolAddress((void**)&p_W1T, g_W1T_h);
    cudaGetSymbolAddress((void**)&p_W2T, g_W2T_h);

    cudaFuncSetAttribute(tgemm<0,1,1,0>, cudaFuncAttributeMaxDynamicSharedMemorySize, TG_SMEM);
    cudaFuncSetAttribute(tgemm<0,0,1,1>, cudaFuncAttributeMaxDynamicSharedMemorySize, TG_SMEM);
    cudaFuncSetAttribute(tgemm<0,0,SPLK,0>, cudaFuncAttributeMaxDynamicSharedMemorySize, TG_SMEM);
    cudaFuncSetAttribute(tgemm<3,1,1,0>, cudaFuncAttributeMaxDynamicSharedMemorySize, TG_SMEM);
    cudaFuncSetAttribute(tgemm<4,0,1,0>, cudaFuncAttributeMaxDynamicSharedMemorySize, TG_SMEM);
    cudaFuncSetAttribute(attn_gemm, cudaFuncAttributeMaxDynamicSharedMemorySize, AT_SMEM);

    dim3 tb32(32, 8);

    // weight transposes (one-time)
    transpose_w<<<dim3(D_/32,   D_/32),   tb32>>>(Wq, p_WqT, D_,   D_);
    transpose_w<<<dim3(D_/32,   C_/32),   tb32>>>(Wk, p_WkT, C_,   D_);
    transpose_w<<<dim3(D_/32,   C_/32),   tb32>>>(Wv, p_WvT, C_,   D_);
    transpose_w<<<dim3(MLP_/32, D_/32),   tb32>>>(W1, p_W1T, D_,   MLP_);
    transpose_w<<<dim3(D_/32,   MLP_/32), tb32>>>(W2, p_W2T, MLP_, D_);

    // fused input LN (stats + transpose + normalize)
    norm_input<<<dim3(L_/32, B_), tb32>>>(x, lin_g, lin_b);

    // k projection (half out); v projection writes v^T directly (OUTT)
    tgemm<0,1,1,0><<<dim3(D_/128, (B_*L_)/128, 1), 256, TG_SMEM>>>(
        p_xn, p_WkT, p_k, C_, C_, D_, 0, 0, 0, nullptr, nullptr, 1.f);
    tgemm<0,0,1,1><<<dim3(D_/128, (B_*L_)/128, 1), 256, TG_SMEM>>>(
        p_xn, p_WvT, p_vT, C_, C_, L_, 0, 0, 0, nullptr, nullptr, 1.f);

    bcast_tmpl<<<(B_ * N_ * D_) / 256, 256>>>(ti);

    for (int it = 0; it < TITER; it++) {
        // t = LN(templates); q = (t @ Wq) * scale  (half out)
        ln_rows<<<B_ * N_, 256>>>(p_tmpl, p_t2, lt_g, lt_b);
        tgemm<0,1,1,0><<<dim3(D_/128, (B_*N_)/128, 1), 256, TG_SMEM>>>(
            p_t2, p_WqT, p_q, D_, D_, D_, 0, 0, 0, nullptr, nullptr, SCALE_);

        // fused logits GEMM + softmax + attnT + colsum partials
        attn_gemm<<<dim3(1, L_/128, B_), 256, AT_SMEM>>>();

        // update: split-K partials of attn^T @ v
        tgemm<0,0,SPLK,0><<<dim3(D_/128, N_/128, B_ * SPLK), 256, TG_SMEM>>>(
            p_attnT, p_vT, p_part, L_, L_ / SPLK, D_,
            (long long)N_ * L_, (long long)D_ * L_, (long long)N_ * D_,
            nullptr, nullptr, 1.f);

        // fused colsum-finalize + reduce + residual + LN(lm) -> t2
        update_ln<<<B_ * N_, 256>>>(lm_g, lm_b);

        // MLP on t2: templates += relu(t2@W1+b1)@W2 + b2
        tgemm<3,1,1,0><<<dim3(MLP_/128, (B_*N_)/128, 1), 256, TG_SMEM>>>(
            p_t2, p_W1T, p_h, D_, D_, MLP_, 0, 0, 0, nullptr, b1, 1.f);
        tgemm<4,0,1,0><<<dim3(D_/128, (B_*N_)/128, 1), 256, TG_SMEM>>>(
            p_h, p_W2T, p_tmpl, MLP_, MLP_, D_, 0, 0, 0, p_tmpl, b2, 1.f);
    }

    out_templates_k<<<dim3(N_ / 32, D_ / 32, B_), tb32>>>(out_t);
    out_attn_k<<<(B_ * N_ * L_) / 256, 256>>>(out_a);
}